// round 1
// baseline (speedup 1.0000x reference)
#include <cuda_runtime.h>
#include <math.h>

#define T_SEQ 1024
#define C_DIM 768
#define NH    12
#define HS    64
#define C3    (3 * C_DIM)   // 2304

// Scratch (allocation-free rule: __device__ globals)
__device__ float g_qkv[T_SEQ * C3];      // [T, 3C]
__device__ float g_y[T_SEQ * C_DIM];     // [T, C] attention output

// ---------------------------------------------------------------------------
// SGEMM: C[M,N] = A[M,K] @ B[K,N] + bias[N]   (all row-major, fp32)
// 128x128 block tile, K-tile 8, 256 threads, 8x8 register microtile.
// Requires: M%128==0, N%128==0, K%8==0 (true for all our shapes).
// ---------------------------------------------------------------------------
#define GBM 128
#define GBN 128
#define GBK 8
#define GTM 8
#define GTN 8

__global__ __launch_bounds__(256, 2)
void sgemm_bias(int M, int N, int K,
                const float* __restrict__ A,
                const float* __restrict__ B,
                const float* __restrict__ bias,
                float* __restrict__ Cc)
{
    __shared__ float As[GBK][GBM];
    __shared__ float Bs[GBK][GBN];

    const int tid  = threadIdx.x;
    const int cRow = blockIdx.y;
    const int cCol = blockIdx.x;

    const int threadCol = tid % (GBN / GTN);   // 0..15
    const int threadRow = tid / (GBN / GTN);   // 0..15

    const float* Ap = A + (size_t)cRow * GBM * K;
    const float* Bp = B + (size_t)cCol * GBN;

    // A tile load mapping: 128 rows x 8 cols = 256 float4 (one per thread)
    const int innerRowA = tid >> 1;        // 0..127
    const int innerColA = tid & 1;         // 0..1  (float4 granularity)
    // B tile load mapping: 8 rows x 128 cols = 256 float4
    const int innerRowB = tid >> 5;        // 0..7
    const int innerColB = tid & 31;        // 0..31

    float res[GTM][GTN];
#pragma unroll
    for (int i = 0; i < GTM; i++)
#pragma unroll
        for (int j = 0; j < GTN; j++) res[i][j] = 0.0f;

    float regM[GTM], regN[GTN];

    for (int bk = 0; bk < K; bk += GBK) {
        float4 a4 = *(const float4*)(Ap + (size_t)innerRowA * K + innerColA * 4);
        As[innerColA * 4 + 0][innerRowA] = a4.x;
        As[innerColA * 4 + 1][innerRowA] = a4.y;
        As[innerColA * 4 + 2][innerRowA] = a4.z;
        As[innerColA * 4 + 3][innerRowA] = a4.w;

        *(float4*)(&Bs[innerRowB][innerColB * 4]) =
            *(const float4*)(Bp + (size_t)innerRowB * N + innerColB * 4);

        __syncthreads();
        Ap += GBK;
        Bp += (size_t)GBK * N;

#pragma unroll
        for (int k = 0; k < GBK; k++) {
#pragma unroll
            for (int i = 0; i < GTM; i++) regM[i] = As[k][threadRow * GTM + i];
#pragma unroll
            for (int j = 0; j < GTN; j++) regN[j] = Bs[k][threadCol * GTN + j];
#pragma unroll
            for (int i = 0; i < GTM; i++)
#pragma unroll
                for (int j = 0; j < GTN; j++)
                    res[i][j] += regM[i] * regN[j];
        }
        __syncthreads();
    }

#pragma unroll
    for (int i = 0; i < GTM; i++) {
        const int row = cRow * GBM + threadRow * GTM + i;
#pragma unroll
        for (int j = 0; j < GTN; j += 4) {
            const int col = cCol * GBN + threadCol * GTN + j;
            float4 b4 = *(const float4*)(bias + col);
            float4 r;
            r.x = res[i][j + 0] + b4.x;
            r.y = res[i][j + 1] + b4.y;
            r.z = res[i][j + 2] + b4.z;
            r.w = res[i][j + 3] + b4.w;
            *(float4*)(Cc + (size_t)row * N + col) = r;
        }
    }
}

// ---------------------------------------------------------------------------
// Flash attention (fp32, causal). Block = (q-tile of 64, head). 256 threads.
// Thread (tR=tid/16, tC=tid%16) owns rows {tR+16i} and cols {tC+16j}, i,j<4.
// The +16 stride makes every inner-loop LDS conflict-free with pad 65.
// ---------------------------------------------------------------------------
#define BQ  64
#define BKV 64
#define PAD 65

extern __shared__ float sm_attn[];

__global__ __launch_bounds__(256)
void attn_kernel(const float* __restrict__ qkv, float* __restrict__ y)
{
    float* Qs = sm_attn;                 // [64][PAD]
    float* Ks = Qs + BQ * PAD;           // [64][PAD]
    float* Vs = Ks + BKV * PAD;          // [64][PAD]
    float* Ps = Vs + BKV * PAD;          // [key j][row r] : [64][PAD]

    const int tid = threadIdx.x;
    const int tR  = tid >> 4;            // 0..15
    const int tC  = tid & 15;            // 0..15
    const int h   = blockIdx.y;
    const int qt  = blockIdx.x;
    const int q0  = qt * BQ;

    // Load Q tile: Qs[r][d] = qkv[(q0+r)*C3 + h*HS + d]
    for (int idx = tid; idx < BQ * (HS / 4); idx += 256) {
        const int r  = idx >> 4;         // HS/4 = 16
        const int c4 = (idx & 15) * 4;
        float4 v4 = *(const float4*)(qkv + (size_t)(q0 + r) * C3 + h * HS + c4);
        Qs[r * PAD + c4 + 0] = v4.x;
        Qs[r * PAD + c4 + 1] = v4.y;
        Qs[r * PAD + c4 + 2] = v4.z;
        Qs[r * PAD + c4 + 3] = v4.w;
    }

    float m[4], l[4], acc[4][4];
#pragma unroll
    for (int i = 0; i < 4; i++) {
        m[i] = -1e30f; l[i] = 0.0f;
#pragma unroll
        for (int j = 0; j < 4; j++) acc[i][j] = 0.0f;
    }

    const float scale = 0.125f;          // 1/sqrt(64)

    for (int kt = 0; kt <= qt; kt++) {
        const int j0 = kt * BKV;
        __syncthreads();   // protect Ks/Vs (readers of previous tile done)

        // Load K, V tiles
        for (int idx = tid; idx < BKV * (HS / 4); idx += 256) {
            const int r  = idx >> 4;
            const int c4 = (idx & 15) * 4;
            const size_t base = (size_t)(j0 + r) * C3 + h * HS + c4;
            float4 k4 = *(const float4*)(qkv + base + C_DIM);
            Ks[r * PAD + c4 + 0] = k4.x;
            Ks[r * PAD + c4 + 1] = k4.y;
            Ks[r * PAD + c4 + 2] = k4.z;
            Ks[r * PAD + c4 + 3] = k4.w;
            float4 v4 = *(const float4*)(qkv + base + 2 * C_DIM);
            Vs[r * PAD + c4 + 0] = v4.x;
            Vs[r * PAD + c4 + 1] = v4.y;
            Vs[r * PAD + c4 + 2] = v4.z;
            Vs[r * PAD + c4 + 3] = v4.w;
        }
        __syncthreads();

        // S = Q K^T for this thread's 4x4 microtile
        float s[4][4];
#pragma unroll
        for (int i = 0; i < 4; i++)
#pragma unroll
            for (int j = 0; j < 4; j++) s[i][j] = 0.0f;

        for (int d = 0; d < HS; d++) {
            float qreg[4], kreg[4];
#pragma unroll
            for (int i = 0; i < 4; i++) qreg[i] = Qs[(tR + 16 * i) * PAD + d];
#pragma unroll
            for (int j = 0; j < 4; j++) kreg[j] = Ks[(tC + 16 * j) * PAD + d];
#pragma unroll
            for (int i = 0; i < 4; i++)
#pragma unroll
                for (int j = 0; j < 4; j++)
                    s[i][j] += qreg[i] * kreg[j];
        }

        // scale + causal mask
#pragma unroll
        for (int i = 0; i < 4; i++) {
            const int grow = q0 + tR + 16 * i;
#pragma unroll
            for (int j = 0; j < 4; j++) {
                const int gcol = j0 + tC + 16 * j;
                s[i][j] = (gcol > grow) ? -1e30f : s[i][j] * scale;
            }
        }

        // online softmax per row group (16-lane shuffle groups)
#pragma unroll
        for (int i = 0; i < 4; i++) {
            float mloc = s[i][0];
#pragma unroll
            for (int j = 1; j < 4; j++) mloc = fmaxf(mloc, s[i][j]);
#pragma unroll
            for (int off = 8; off >= 1; off >>= 1)
                mloc = fmaxf(mloc, __shfl_xor_sync(0xffffffffu, mloc, off));
            const float mnew = fmaxf(m[i], mloc);
            const float corr = __expf(m[i] - mnew);

            float psum = 0.0f;
            float p[4];
#pragma unroll
            for (int j = 0; j < 4; j++) {
                p[j] = __expf(s[i][j] - mnew);
                psum += p[j];
            }
#pragma unroll
            for (int off = 8; off >= 1; off >>= 1)
                psum += __shfl_xor_sync(0xffffffffu, psum, off);

            l[i] = l[i] * corr + psum;
            m[i] = mnew;
#pragma unroll
            for (int j = 0; j < 4; j++) acc[i][j] *= corr;
#pragma unroll
            for (int j = 0; j < 4; j++)
                Ps[(tC + 16 * j) * PAD + (tR + 16 * i)] = p[j];
        }
        __syncthreads();   // Ps visible to all

        // O += P @ V  (thread microtile: rows tR+16i, dims tC+16j)
        for (int j = 0; j < BKV; j++) {
            float pr[4], vr[4];
#pragma unroll
            for (int i = 0; i < 4; i++) pr[i] = Ps[j * PAD + (tR + 16 * i)];
#pragma unroll
            for (int jj = 0; jj < 4; jj++) vr[jj] = Vs[j * PAD + (tC + 16 * jj)];
#pragma unroll
            for (int i = 0; i < 4; i++)
#pragma unroll
                for (int jj = 0; jj < 4; jj++)
                    acc[i][jj] += pr[i] * vr[jj];
        }
    }

    // finalize + write y[t][h*HS + d]
#pragma unroll
    for (int i = 0; i < 4; i++) {
        const float inv_l = 1.0f / l[i];
        const int grow = q0 + tR + 16 * i;
#pragma unroll
        for (int jj = 0; jj < 4; jj++) {
            const int d = tC + 16 * jj;
            y[(size_t)grow * C_DIM + h * HS + d] = acc[i][jj] * inv_l;
        }
    }
}

// ---------------------------------------------------------------------------
extern "C" void kernel_launch(void* const* d_in, const int* in_sizes, int n_in,
                              void* d_out, int out_size)
{
    const float* x      = (const float*)d_in[0];   // [1,1024,768]
    const float* W_attn = (const float*)d_in[1];   // [768, 2304]
    const float* b_attn = (const float*)d_in[2];   // [2304]
    const float* W_proj = (const float*)d_in[3];   // [768, 768]
    const float* b_proj = (const float*)d_in[4];   // [768]
    float* out = (float*)d_out;                    // [1,1024,768]

    float *qkv, *y;
    cudaGetSymbolAddress((void**)&qkv, g_qkv);
    cudaGetSymbolAddress((void**)&y, g_y);

    const int attn_smem = 4 * BQ * PAD * (int)sizeof(float);   // 66560 B
    cudaFuncSetAttribute(attn_kernel,
                         cudaFuncAttributeMaxDynamicSharedMemorySize, attn_smem);

    // 1) qkv = x @ W_attn + b_attn   [1024, 2304]
    {
        dim3 grid(C3 / GBN, T_SEQ / GBM);
        sgemm_bias<<<grid, 256>>>(T_SEQ, C3, C_DIM, x, W_attn, b_attn, qkv);
    }

    // 2) per-head causal flash attention -> y [1024, 768]
    {
        dim3 grid(T_SEQ / BQ, NH);
        attn_kernel<<<grid, 256, attn_smem>>>(qkv, y);
    }

    // 3) out = y @ W_proj + b_proj   [1024, 768]
    {
        dim3 grid(C_DIM / GBN, T_SEQ / GBM);
        sgemm_bias<<<grid, 256>>>(T_SEQ, C_DIM, C_DIM, y, W_proj, b_proj, out);
    }
}

// round 2
// speedup vs baseline: 1.5548x; 1.5548x over previous
#include <cuda_runtime.h>
#include <math.h>

#define T_SEQ 1024
#define C_DIM 768
#define NH    12
#define HS    64
#define C3    (3 * C_DIM)   // 2304

typedef unsigned long long ull;

// Scratch (allocation-free rule: __device__ globals)
__device__ float g_qkv[T_SEQ * C3];      // [T, 3C]
__device__ float g_y[T_SEQ * C_DIM];     // [T, C] attention output

// ---------------------------------------------------------------------------
// Packed f32x2 helpers (Blackwell dual-rate fp32; ptxas never auto-fuses)
// ---------------------------------------------------------------------------
__device__ __forceinline__ ull pk2(float lo, float hi) {
    ull r;
    asm("mov.b64 %0, {%1, %2};" : "=l"(r) : "f"(lo), "f"(hi));
    return r;
}
__device__ __forceinline__ void fma2(ull& d, ull a, ull b) {
    asm("fma.rn.f32x2 %0, %1, %2, %0;" : "+l"(d) : "l"(a), "l"(b));
}
__device__ __forceinline__ void mul2(ull& d, ull a, ull b) {
    asm("mul.rn.f32x2 %0, %1, %2;" : "=l"(d) : "l"(a), "l"(b));
}
__device__ __forceinline__ float2 upk(ull v) {
    float2 f;
    asm("mov.b64 {%0, %1}, %2;" : "=f"(f.x), "=f"(f.y) : "l"(v));
    return f;
}

// ---------------------------------------------------------------------------
// SGEMM: C[M,N] = A[M,K] @ B[K,N] + bias[N]  (row-major fp32)
// Templated tile; 256 threads; double-buffered smem; f32x2 microtile.
// Requires M%BM==0, N%BN==0, K%BK==0.
// ---------------------------------------------------------------------------
template<int BM, int BN, int BK, int TM, int TN>
__global__ __launch_bounds__(256)
void sgemm_f32x2(int M, int N, int K,
                 const float* __restrict__ A,
                 const float* __restrict__ B,
                 const float* __restrict__ bias,
                 float* __restrict__ C)
{
    constexpr int APAD = 4;
    __shared__ float As[2][BK][BM + APAD];   // transposed: As[k][m]
    __shared__ float Bs[2][BK][BN];

    const int tid  = threadIdx.x;
    const int cRow = blockIdx.y;
    const int cCol = blockIdx.x;

    constexpr int TCN = BN / TN;             // threads along N
    const int tCol = tid % TCN;
    const int tRow = tid / TCN;

    constexpr int LA = (BM * BK) / (4 * 256);   // float4 loads per thread (A)
    constexpr int LB = (BN * BK) / (4 * 256);   // float4 loads per thread (B)
    static_assert(LA >= 1 && LB >= 1, "tile too small");

    const float* Ap = A + (size_t)cRow * BM * K;
    const float* Bp = B + (size_t)cCol * BN;

    ull acc[TM][TN / 2];
#pragma unroll
    for (int i = 0; i < TM; i++)
#pragma unroll
        for (int j = 0; j < TN / 2; j++) acc[i][j] = 0ull;

    float4 ra[LA], rb[LB];
    const int nk = K / BK;

    // ---- prologue: load tile 0 into smem buf 0
#pragma unroll
    for (int it = 0; it < LA; it++) {
        const int idx = tid + it * 256;
        const int row = idx / (BK / 4);
        const int c4  = idx % (BK / 4);
        ra[it] = *(const float4*)(Ap + (size_t)row * K + c4 * 4);
    }
#pragma unroll
    for (int it = 0; it < LB; it++) {
        const int idx = tid + it * 256;
        const int row = idx / (BN / 4);
        const int n4  = idx % (BN / 4);
        rb[it] = *(const float4*)(Bp + (size_t)row * N + n4 * 4);
    }
#pragma unroll
    for (int it = 0; it < LA; it++) {
        const int idx = tid + it * 256;
        const int row = idx / (BK / 4);
        const int c4  = idx % (BK / 4);
        As[0][c4 * 4 + 0][row] = ra[it].x;
        As[0][c4 * 4 + 1][row] = ra[it].y;
        As[0][c4 * 4 + 2][row] = ra[it].z;
        As[0][c4 * 4 + 3][row] = ra[it].w;
    }
#pragma unroll
    for (int it = 0; it < LB; it++) {
        const int idx = tid + it * 256;
        const int row = idx / (BN / 4);
        const int n4  = idx % (BN / 4);
        *(float4*)&Bs[0][row][n4 * 4] = rb[it];
    }
    __syncthreads();

    for (int kt = 0; kt < nk; kt++) {
        // prefetch next tile to registers (global latency overlapped w/ compute)
        if (kt + 1 < nk) {
#pragma unroll
            for (int it = 0; it < LA; it++) {
                const int idx = tid + it * 256;
                const int row = idx / (BK / 4);
                const int c4  = idx % (BK / 4);
                ra[it] = *(const float4*)(Ap + (size_t)row * K + (kt + 1) * BK + c4 * 4);
            }
#pragma unroll
            for (int it = 0; it < LB; it++) {
                const int idx = tid + it * 256;
                const int row = idx / (BN / 4);
                const int n4  = idx % (BN / 4);
                rb[it] = *(const float4*)(Bp + (size_t)((kt + 1) * BK + row) * N + n4 * 4);
            }
        }

        const int buf = kt & 1;
#pragma unroll
        for (int k = 0; k < BK; k++) {
            float a[TM], b[TN];
#pragma unroll
            for (int m4 = 0; m4 < TM / 4; m4++) {
                float4 v = *(const float4*)&As[buf][k][tRow * TM + m4 * 4];
                a[m4 * 4 + 0] = v.x; a[m4 * 4 + 1] = v.y;
                a[m4 * 4 + 2] = v.z; a[m4 * 4 + 3] = v.w;
            }
#pragma unroll
            for (int n4 = 0; n4 < TN / 4; n4++) {
                float4 v = *(const float4*)&Bs[buf][k][tCol * TN + n4 * 4];
                b[n4 * 4 + 0] = v.x; b[n4 * 4 + 1] = v.y;
                b[n4 * 4 + 2] = v.z; b[n4 * 4 + 3] = v.w;
            }
            ull bp[TN / 2];
#pragma unroll
            for (int n2 = 0; n2 < TN / 2; n2++) bp[n2] = pk2(b[2 * n2], b[2 * n2 + 1]);
#pragma unroll
            for (int i = 0; i < TM; i++) {
                const ull ap = pk2(a[i], a[i]);
#pragma unroll
                for (int n2 = 0; n2 < TN / 2; n2++) fma2(acc[i][n2], ap, bp[n2]);
            }
        }

        // stage next tile into other buffer
        if (kt + 1 < nk) {
            const int nb = (kt + 1) & 1;
#pragma unroll
            for (int it = 0; it < LA; it++) {
                const int idx = tid + it * 256;
                const int row = idx / (BK / 4);
                const int c4  = idx % (BK / 4);
                As[nb][c4 * 4 + 0][row] = ra[it].x;
                As[nb][c4 * 4 + 1][row] = ra[it].y;
                As[nb][c4 * 4 + 2][row] = ra[it].z;
                As[nb][c4 * 4 + 3][row] = ra[it].w;
            }
#pragma unroll
            for (int it = 0; it < LB; it++) {
                const int idx = tid + it * 256;
                const int row = idx / (BN / 4);
                const int n4  = idx % (BN / 4);
                *(float4*)&Bs[nb][row][n4 * 4] = rb[it];
            }
        }
        __syncthreads();
    }

    // epilogue: bias + store
#pragma unroll
    for (int i = 0; i < TM; i++) {
        const int row = cRow * BM + tRow * TM + i;
#pragma unroll
        for (int n2 = 0; n2 < TN / 2; n2++) {
            const int col = cCol * BN + tCol * TN + 2 * n2;
            float2 v = upk(acc[i][n2]);
            float2 r;
            r.x = v.x + bias[col];
            r.y = v.y + bias[col + 1];
            *(float2*)(C + (size_t)row * N + col) = r;
        }
    }
}

// ---------------------------------------------------------------------------
// Flash attention (fp32, causal), f32x2 + float4-vectorized LDS.
// Block b: qt = 15 - b/12 (descending: long blocks in wave 1), h = b%12.
// 256 threads. tR=tid/16, tC=tid%16.
//   S microtile:  rows tR+16i (i<4), keys tC+16j (j<4)
//   PV microtile: rows tR+16i (i<4), dims tC*4+jj (jj<4, contiguous)
// ---------------------------------------------------------------------------
#define BQ   64
#define BKV  64
#define PADA 68   // multiple of 4 (float4 alignment), 68%32=4 -> <=2-way conflicts

extern __shared__ float sm_attn[];

__global__ __launch_bounds__(256)
void attn_kernel(const float* __restrict__ qkv, float* __restrict__ y)
{
    float* Qs = sm_attn;                  // [64][PADA]
    float* Ks = Qs + BQ * PADA;           // [64][PADA]
    float* Vs = Ks + BKV * PADA;          // [64][PADA]
    float* Ps = Vs + BKV * PADA;          // [row][key] : [64][PADA]

    const int tid = threadIdx.x;
    const int tR  = tid >> 4;             // 0..15
    const int tC  = tid & 15;             // 0..15
    const int b   = blockIdx.x;
    const int qt  = 15 - (b / NH);
    const int h   = b % NH;
    const int q0  = qt * BQ;

    // Load Q tile (float4)
#pragma unroll
    for (int it = 0; it < 4; it++) {
        const int idx = tid + it * 256;
        const int r   = idx >> 4;         // 0..63
        const int c4  = (idx & 15) * 4;
        float4 v4 = *(const float4*)(qkv + (size_t)(q0 + r) * C3 + h * HS + c4);
        *(float4*)&Qs[r * PADA + c4] = v4;
    }

    float m[4], l[4];
    ull accO[4][2];
#pragma unroll
    for (int i = 0; i < 4; i++) {
        m[i] = -1e30f; l[i] = 0.0f;
        accO[i][0] = 0ull; accO[i][1] = 0ull;
    }

    const float scale = 0.125f;           // 1/sqrt(64)

    for (int kt = 0; kt <= qt; kt++) {
        const int j0 = kt * BKV;
        __syncthreads();                  // prev-iter readers of Ks/Vs/Ps done

        // Load K, V tiles (float4)
#pragma unroll
        for (int it = 0; it < 4; it++) {
            const int idx = tid + it * 256;
            const int r   = idx >> 4;
            const int c4  = (idx & 15) * 4;
            const size_t base = (size_t)(j0 + r) * C3 + h * HS + c4;
            *(float4*)&Ks[r * PADA + c4] = *(const float4*)(qkv + base + C_DIM);
            *(float4*)&Vs[r * PADA + c4] = *(const float4*)(qkv + base + 2 * C_DIM);
        }
        __syncthreads();

        // ---- S = Q K^T (f32x2, float4 LDS)
        ull s2[4][2];
#pragma unroll
        for (int i = 0; i < 4; i++) { s2[i][0] = 0ull; s2[i][1] = 0ull; }

#pragma unroll 4
        for (int d4 = 0; d4 < HS / 4; d4++) {
            float4 qv[4], kv[4];
#pragma unroll
            for (int i = 0; i < 4; i++)
                qv[i] = *(const float4*)&Qs[(tR + 16 * i) * PADA + d4 * 4];
#pragma unroll
            for (int j = 0; j < 4; j++)
                kv[j] = *(const float4*)&Ks[(tC + 16 * j) * PADA + d4 * 4];
            const float* qf = (const float*)qv;
            const float* kf = (const float*)kv;
#pragma unroll
            for (int dd = 0; dd < 4; dd++) {
                ull kp0 = pk2(kf[0 * 4 + dd], kf[1 * 4 + dd]);
                ull kp1 = pk2(kf[2 * 4 + dd], kf[3 * 4 + dd]);
#pragma unroll
                for (int i = 0; i < 4; i++) {
                    const ull qq = pk2(qf[i * 4 + dd], qf[i * 4 + dd]);
                    fma2(s2[i][0], qq, kp0);
                    fma2(s2[i][1], qq, kp1);
                }
            }
        }

        // unpack, scale + causal mask
        float s[4][4];
#pragma unroll
        for (int i = 0; i < 4; i++) {
            float2 f0 = upk(s2[i][0]);
            float2 f1 = upk(s2[i][1]);
            s[i][0] = f0.x; s[i][1] = f0.y; s[i][2] = f1.x; s[i][3] = f1.y;
        }
#pragma unroll
        for (int i = 0; i < 4; i++) {
            const int grow = q0 + tR + 16 * i;
#pragma unroll
            for (int j = 0; j < 4; j++) {
                const int gcol = j0 + tC + 16 * j;
                s[i][j] = (gcol > grow) ? -1e30f : s[i][j] * scale;
            }
        }

        // online softmax (16-lane groups share a row)
#pragma unroll
        for (int i = 0; i < 4; i++) {
            float mloc = fmaxf(fmaxf(s[i][0], s[i][1]), fmaxf(s[i][2], s[i][3]));
#pragma unroll
            for (int off = 8; off >= 1; off >>= 1)
                mloc = fmaxf(mloc, __shfl_xor_sync(0xffffffffu, mloc, off));
            const float mnew = fmaxf(m[i], mloc);
            const float corr = __expf(m[i] - mnew);

            float p[4], psum = 0.0f;
#pragma unroll
            for (int j = 0; j < 4; j++) { p[j] = __expf(s[i][j] - mnew); psum += p[j]; }
#pragma unroll
            for (int off = 8; off >= 1; off >>= 1)
                psum += __shfl_xor_sync(0xffffffffu, psum, off);

            l[i] = l[i] * corr + psum;
            m[i] = mnew;
            const ull cp = pk2(corr, corr);
            mul2(accO[i][0], accO[i][0], cp);
            mul2(accO[i][1], accO[i][1], cp);
            const int row = tR + 16 * i;
#pragma unroll
            for (int j = 0; j < 4; j++)
                Ps[row * PADA + (tC + 16 * j)] = p[j];
        }
        __syncthreads();                  // Ps visible

        // ---- O += P @ V (f32x2, float4 LDS; dims tC*4..tC*4+3)
#pragma unroll 4
        for (int j4 = 0; j4 < BKV / 4; j4++) {
            float4 pv[4], vv[4];
#pragma unroll
            for (int i = 0; i < 4; i++)
                pv[i] = *(const float4*)&Ps[(tR + 16 * i) * PADA + j4 * 4];
#pragma unroll
            for (int kk = 0; kk < 4; kk++)
                vv[kk] = *(const float4*)&Vs[(j4 * 4 + kk) * PADA + tC * 4];
            const float* pf = (const float*)pv;
#pragma unroll
            for (int kk = 0; kk < 4; kk++) {
                const ull vp0 = pk2(vv[kk].x, vv[kk].y);
                const ull vp1 = pk2(vv[kk].z, vv[kk].w);
#pragma unroll
                for (int i = 0; i < 4; i++) {
                    const ull pp = pk2(pf[i * 4 + kk], pf[i * 4 + kk]);
                    fma2(accO[i][0], pp, vp0);
                    fma2(accO[i][1], pp, vp1);
                }
            }
        }
    }

    // finalize + write y (float4 per row: dims tC*4..+3)
#pragma unroll
    for (int i = 0; i < 4; i++) {
        const float inv_l = 1.0f / l[i];
        const int grow = q0 + tR + 16 * i;
        float2 f0 = upk(accO[i][0]);
        float2 f1 = upk(accO[i][1]);
        float4 r;
        r.x = f0.x * inv_l; r.y = f0.y * inv_l;
        r.z = f1.x * inv_l; r.w = f1.y * inv_l;
        *(float4*)(y + (size_t)grow * C_DIM + h * HS + tC * 4) = r;
    }
}

// ---------------------------------------------------------------------------
extern "C" void kernel_launch(void* const* d_in, const int* in_sizes, int n_in,
                              void* d_out, int out_size)
{
    const float* x      = (const float*)d_in[0];   // [1,1024,768]
    const float* W_attn = (const float*)d_in[1];   // [768, 2304]
    const float* b_attn = (const float*)d_in[2];   // [2304]
    const float* W_proj = (const float*)d_in[3];   // [768, 768]
    const float* b_proj = (const float*)d_in[4];   // [768]
    float* out = (float*)d_out;                    // [1,1024,768]

    float *qkv, *y;
    cudaGetSymbolAddress((void**)&qkv, g_qkv);
    cudaGetSymbolAddress((void**)&y, g_y);

    const int attn_smem = 4 * BQ * PADA * (int)sizeof(float);   // 69632 B
    cudaFuncSetAttribute(attn_kernel,
                         cudaFuncAttributeMaxDynamicSharedMemorySize, attn_smem);

    // 1) qkv = x @ W_attn + b_attn   [1024, 2304]
    {
        dim3 grid(C3 / 128, T_SEQ / 128);   // (18, 8) = 144 CTAs
        sgemm_f32x2<128, 128, 16, 8, 8><<<grid, 256>>>(T_SEQ, C3, C_DIM,
                                                       x, W_attn, b_attn, qkv);
    }

    // 2) per-head causal flash attention -> y [1024, 768]
    {
        attn_kernel<<<T_SEQ / BQ * NH, 256, attn_smem>>>(qkv, y);
    }

    // 3) out = y @ W_proj + b_proj   [1024, 768]
    {
        dim3 grid(C_DIM / 64, T_SEQ / 64);  // (12, 16) = 192 CTAs
        sgemm_f32x2<64, 64, 16, 4, 4><<<grid, 256>>>(T_SEQ, C_DIM, C_DIM,
                                                     y, W_proj, b_proj, out);
    }
}

// round 4
// speedup vs baseline: 1.9498x; 1.2541x over previous
#include <cuda_runtime.h>
#include <cstdint>
#include <math.h>

#define T_SEQ 1024
#define C_DIM 768
#define NH    12
#define HS    64
#define C3    (3 * C_DIM)   // 2304

typedef unsigned long long ull;

// Scratch (allocation-free rule: __device__ globals)
__device__ float g_qkv[T_SEQ * C3];      // [T, 3C]
__device__ float g_y[T_SEQ * C_DIM];     // [T, C] attention output

// ---------------------------------------------------------------------------
// f32x2 helpers
// ---------------------------------------------------------------------------
__device__ __forceinline__ ull pk2(float lo, float hi) {
    ull r; asm("mov.b64 %0, {%1, %2};" : "=l"(r) : "f"(lo), "f"(hi)); return r;
}
__device__ __forceinline__ void fma2(ull& d, ull a, ull b) {
    asm("fma.rn.f32x2 %0, %1, %2, %0;" : "+l"(d) : "l"(a), "l"(b));
}
__device__ __forceinline__ void mul2(ull& d, ull a, ull b) {
    asm("mul.rn.f32x2 %0, %1, %2;" : "=l"(d) : "l"(a), "l"(b));
}
__device__ __forceinline__ float2 upk(ull v) {
    float2 f; asm("mov.b64 {%0, %1}, %2;" : "=f"(f.x), "=f"(f.y) : "l"(v)); return f;
}

// ---------------------------------------------------------------------------
// tf32 mma.sync helpers (baseline PTX, compiles at compute_100)
// ---------------------------------------------------------------------------
__device__ __forceinline__ uint32_t to_tf32(float f) {
    uint32_t u; asm("cvt.rna.tf32.f32 %0, %1;" : "=r"(u) : "f"(f)); return u;
}
__device__ __forceinline__ void mma_tf32(float* c, const uint32_t* a, const uint32_t* b) {
    asm volatile(
        "mma.sync.aligned.m16n8k8.row.col.f32.tf32.tf32.f32 "
        "{%0,%1,%2,%3},{%4,%5,%6,%7},{%8,%9},{%0,%1,%2,%3};"
        : "+f"(c[0]), "+f"(c[1]), "+f"(c[2]), "+f"(c[3])
        : "r"(a[0]), "r"(a[1]), "r"(a[2]), "r"(a[3]), "r"(b[0]), "r"(b[1]));
}

extern __shared__ char sm_dyn[];

// ---------------------------------------------------------------------------
// tf32 tensor-core GEMM: C[M,N] = A[M,K] @ B[K,N] + bias[N]  (row-major fp32)
// Block tile BM x BN, BK=32 (4 k8-steps), 256 threads = 8 warps (2 x 4).
// SMEM stores tf32 values in fragment-pair layout:
//   row stride RS=40 floats; within k-step s, offset s*8 + cc*2 holds
//   (col k0+s*8+cc, col k0+s*8+cc+4)  -> every fragment = 1 conflict-free LDS.64
// ---------------------------------------------------------------------------
template<int BM, int BN>
__global__ __launch_bounds__(256)
void gemm_mma(int M, int N, int K,
              const float* __restrict__ A,
              const float* __restrict__ B,
              const float* __restrict__ bias,
              float* __restrict__ C)
{
    constexpr int BK = 32;
    constexpr int RS = 40;                 // floats per smem row (conflict-free)
    constexpr int WM = BM / 2;             // warp tile M
    constexpr int WN = BN / 4;             // warp tile N
    constexpr int MT = WM / 16;            // m16 tiles per warp
    constexpr int NT = WN / 8;             // n8 tiles per warp
    constexpr int UA = (BM * 4) / 256;     // A staging units/thread (row, kstep)
    constexpr int UB = (BN * 4) / 256;     // B staging units/thread (n, kstep)
    static_assert(UA >= 1 && UB >= 1, "tile too small");

    float* S = (float*)sm_dyn;
    float* AsB[2] = { S,                      S + (BM + BN) * RS };
    float* BsB[2] = { S + BM * RS,            S + (BM + BN) * RS + BM * RS };

    const int tid = threadIdx.x;
    const int wid = tid >> 5;
    const int lane = tid & 31;
    const int gid = lane >> 2;             // 0..7
    const int tg  = lane & 3;              // 0..3
    const int wm = wid >> 2;               // 0..1
    const int wn = wid & 3;                // 0..3
    const int m0 = blockIdx.y * BM;
    const int n0 = blockIdx.x * BN;

    float acc[MT][NT][4];
#pragma unroll
    for (int i = 0; i < MT; i++)
#pragma unroll
        for (int j = 0; j < NT; j++)
#pragma unroll
            for (int v = 0; v < 4; v++) acc[i][j][v] = 0.0f;

    float4 ra[UA][2];
    float  rb[UB][8];
    const int nk = K / BK;

    // ---------------- staging helpers (as lambdas) ----------------
    auto load_regs = [&](int kc) {
#pragma unroll
        for (int u = 0; u < UA; u++) {
            const int idx = tid + 256 * u;
            const int row = idx >> 2;
            const int s   = idx & 3;
            const float* p = A + (size_t)(m0 + row) * K + kc + s * 8;
            ra[u][0] = *(const float4*)p;
            ra[u][1] = *(const float4*)(p + 4);
        }
#pragma unroll
        for (int u = 0; u < UB; u++) {
            const int idx = tid + 256 * u;
            const int n   = idx % BN;
            const int s   = idx / BN;
            const float* p = B + (size_t)(kc + s * 8) * N + n0 + n;
#pragma unroll
            for (int kk = 0; kk < 8; kk++) rb[u][kk] = p[(size_t)kk * N];
        }
    };
    auto store_smem = [&](int buf) {
        float* As = AsB[buf];
        float* Bs = BsB[buf];
#pragma unroll
        for (int u = 0; u < UA; u++) {
            const int idx = tid + 256 * u;
            const int row = idx >> 2;
            const int s   = idx & 3;
            uint4 w0, w1;
            w0.x = to_tf32(ra[u][0].x); w0.y = to_tf32(ra[u][1].x);
            w0.z = to_tf32(ra[u][0].y); w0.w = to_tf32(ra[u][1].y);
            w1.x = to_tf32(ra[u][0].z); w1.y = to_tf32(ra[u][1].z);
            w1.z = to_tf32(ra[u][0].w); w1.w = to_tf32(ra[u][1].w);
            uint32_t* p = (uint32_t*)&As[row * RS + s * 8];
            *(uint4*)p       = w0;
            *(uint4*)(p + 4) = w1;
        }
#pragma unroll
        for (int u = 0; u < UB; u++) {
            const int idx = tid + 256 * u;
            const int n   = idx % BN;
            const int s   = idx / BN;
            uint4 w0, w1;
            w0.x = to_tf32(rb[u][0]); w0.y = to_tf32(rb[u][4]);
            w0.z = to_tf32(rb[u][1]); w0.w = to_tf32(rb[u][5]);
            w1.x = to_tf32(rb[u][2]); w1.y = to_tf32(rb[u][6]);
            w1.z = to_tf32(rb[u][3]); w1.w = to_tf32(rb[u][7]);
            uint32_t* p = (uint32_t*)&Bs[n * RS + s * 8];
            *(uint4*)p       = w0;
            *(uint4*)(p + 4) = w1;
        }
    };

    // prologue
    load_regs(0);
    store_smem(0);
    __syncthreads();

    for (int i = 0; i < nk; i++) {
        if (i + 1 < nk) load_regs((i + 1) * BK);

        const int buf = i & 1;
        const float* As = AsB[buf];
        const float* Bs = BsB[buf];
#pragma unroll
        for (int s = 0; s < 4; s++) {
            uint32_t af[MT][4], bf[NT][2];
#pragma unroll
            for (int mt = 0; mt < MT; mt++) {
                const int row = wm * WM + mt * 16 + gid;
                const uint32_t* lo = (const uint32_t*)&As[row * RS + s * 8 + tg * 2];
                const uint32_t* hi = (const uint32_t*)&As[(row + 8) * RS + s * 8 + tg * 2];
                af[mt][0] = lo[0]; af[mt][2] = lo[1];
                af[mt][1] = hi[0]; af[mt][3] = hi[1];
            }
#pragma unroll
            for (int nt = 0; nt < NT; nt++) {
                const int n = wn * WN + nt * 8 + gid;
                const uint32_t* bp = (const uint32_t*)&Bs[n * RS + s * 8 + tg * 2];
                bf[nt][0] = bp[0]; bf[nt][1] = bp[1];
            }
#pragma unroll
            for (int mt = 0; mt < MT; mt++)
#pragma unroll
                for (int nt = 0; nt < NT; nt++)
                    mma_tf32(acc[mt][nt], af[mt], bf[nt]);
        }

        if (i + 1 < nk) {
            store_smem(buf ^ 1);
            __syncthreads();
        }
    }

    // epilogue: bias + store (float2 per fragment half)
#pragma unroll
    for (int mt = 0; mt < MT; mt++) {
        const int row = m0 + wm * WM + mt * 16 + gid;
#pragma unroll
        for (int nt = 0; nt < NT; nt++) {
            const int col = n0 + wn * WN + nt * 8 + 2 * tg;
            const float b0 = bias[col], b1 = bias[col + 1];
            float2 r0, r1;
            r0.x = acc[mt][nt][0] + b0; r0.y = acc[mt][nt][1] + b1;
            r1.x = acc[mt][nt][2] + b0; r1.y = acc[mt][nt][3] + b1;
            *(float2*)(C + (size_t)row * N + col)       = r0;
            *(float2*)(C + (size_t)(row + 8) * N + col) = r1;
        }
    }
}

// ---------------------------------------------------------------------------
// Flash attention (fp32, causal): dup-Q / transposed-K / dup-P layouts so all
// f32x2 operands come straight from LDS (zero mov.b64 packing in hot loops).
// Block b: qt = 15 - b/12 (long blocks first), h = b%12. 256 threads.
// Thread (tR=tid/16, tC=tid%16): S rows tR+16i (i<4), keys tC*4+j (j<4);
// PV rows tR+16i, dims tC*4+jj.
// ---------------------------------------------------------------------------
#define QD_STRIDE 66   // ulls per row
#define KT_STRIDE 68   // floats per row
#define SM_QD 0
#define SM_KT (64 * QD_STRIDE * 8)                 // 33792
#define SM_VS (SM_KT + 64 * KT_STRIDE * 4)         // 51200
#define SM_PD (SM_VS + 64 * KT_STRIDE * 4)         // 68608
#define SM_ATTN_TOTAL (SM_PD + 64 * QD_STRIDE * 8) // 102400

__global__ __launch_bounds__(256, 2)
void attn_kernel(const float* __restrict__ qkv, float* __restrict__ y)
{
    char* smem = sm_dyn;
    ull*   Qd = (ull*)(smem + SM_QD);
    float* Kt = (float*)(smem + SM_KT);
    float* Vs = (float*)(smem + SM_VS);
    ull*   Pd = (ull*)(smem + SM_PD);

    const int tid = threadIdx.x;
    const int tR  = tid >> 4;
    const int tC  = tid & 15;
    const int b   = blockIdx.x;
    const int qt  = 15 - (b / NH);
    const int h   = b % NH;
    const int q0  = qt * 64;

    // load Q duplicated: Qd[r][d] = (q,q)
#pragma unroll
    for (int it = 0; it < 4; it++) {
        const int idx = tid + it * 256;
        const int r   = idx >> 4;
        const int c4  = (idx & 15) * 4;
        float4 q = *(const float4*)(qkv + (size_t)(q0 + r) * C3 + h * HS + c4);
        ulonglong2 d0; d0.x = pk2(q.x, q.x); d0.y = pk2(q.y, q.y);
        ulonglong2 d1; d1.x = pk2(q.z, q.z); d1.y = pk2(q.w, q.w);
        *(ulonglong2*)(Qd + r * QD_STRIDE + c4)     = d0;
        *(ulonglong2*)(Qd + r * QD_STRIDE + c4 + 2) = d1;
    }

    float m[4], l[4];
    ull accO[4][2];
#pragma unroll
    for (int i = 0; i < 4; i++) {
        m[i] = -1e30f; l[i] = 0.0f; accO[i][0] = 0ull; accO[i][1] = 0ull;
    }
    const float scale = 0.125f;

    for (int kt = 0; kt <= qt; kt++) {
        const int j0 = kt * 64;
        __syncthreads();

        // load K (transposed) and V
#pragma unroll
        for (int it = 0; it < 4; it++) {
            const int idx = tid + it * 256;
            const int r   = idx >> 4;
            const int c4  = (idx & 15) * 4;
            const size_t base = (size_t)(j0 + r) * C3 + h * HS + c4;
            float4 kv = *(const float4*)(qkv + base + C_DIM);
            Kt[(c4 + 0) * KT_STRIDE + r] = kv.x;
            Kt[(c4 + 1) * KT_STRIDE + r] = kv.y;
            Kt[(c4 + 2) * KT_STRIDE + r] = kv.z;
            Kt[(c4 + 3) * KT_STRIDE + r] = kv.w;
            *(float4*)(Vs + r * KT_STRIDE + c4) = *(const float4*)(qkv + base + 2 * C_DIM);
        }
        __syncthreads();

        // S = Q K^T
        ull s2[4][2];
#pragma unroll
        for (int i = 0; i < 4; i++) { s2[i][0] = 0ull; s2[i][1] = 0ull; }

#pragma unroll 4
        for (int d4 = 0; d4 < 16; d4++) {
            ulonglong2 q01[4], q23[4];
#pragma unroll
            for (int i = 0; i < 4; i++) {
                const ull* qp = Qd + (tR + 16 * i) * QD_STRIDE + d4 * 4;
                q01[i] = *(const ulonglong2*)qp;
                q23[i] = *(const ulonglong2*)(qp + 2);
            }
            ulonglong2 k0 = *(const ulonglong2*)(Kt + (d4 * 4 + 0) * KT_STRIDE + tC * 4);
            ulonglong2 k1 = *(const ulonglong2*)(Kt + (d4 * 4 + 1) * KT_STRIDE + tC * 4);
            ulonglong2 k2 = *(const ulonglong2*)(Kt + (d4 * 4 + 2) * KT_STRIDE + tC * 4);
            ulonglong2 k3 = *(const ulonglong2*)(Kt + (d4 * 4 + 3) * KT_STRIDE + tC * 4);
#pragma unroll
            for (int i = 0; i < 4; i++) {
                fma2(s2[i][0], q01[i].x, k0.x); fma2(s2[i][1], q01[i].x, k0.y);
                fma2(s2[i][0], q01[i].y, k1.x); fma2(s2[i][1], q01[i].y, k1.y);
                fma2(s2[i][0], q23[i].x, k2.x); fma2(s2[i][1], q23[i].x, k2.y);
                fma2(s2[i][0], q23[i].y, k3.x); fma2(s2[i][1], q23[i].y, k3.y);
            }
        }

        // scale + mask + online softmax
#pragma unroll
        for (int i = 0; i < 4; i++) {
            float2 f0 = upk(s2[i][0]);
            float2 f1 = upk(s2[i][1]);
            float s[4] = {f0.x, f0.y, f1.x, f1.y};
            const int grow = q0 + tR + 16 * i;
#pragma unroll
            for (int j = 0; j < 4; j++) {
                const int gcol = j0 + tC * 4 + j;
                s[j] = (gcol > grow) ? -1e30f : s[j] * scale;
            }
            float mloc = fmaxf(fmaxf(s[0], s[1]), fmaxf(s[2], s[3]));
#pragma unroll
            for (int off = 8; off >= 1; off >>= 1)
                mloc = fmaxf(mloc, __shfl_xor_sync(0xffffffffu, mloc, off));
            const float mnew = fmaxf(m[i], mloc);
            const float corr = __expf(m[i] - mnew);
            float p[4], psum = 0.0f;
#pragma unroll
            for (int j = 0; j < 4; j++) { p[j] = __expf(s[j] - mnew); psum += p[j]; }
#pragma unroll
            for (int off = 8; off >= 1; off >>= 1)
                psum += __shfl_xor_sync(0xffffffffu, psum, off);
            l[i] = l[i] * corr + psum;
            m[i] = mnew;
            const ull cp = pk2(corr, corr);
            mul2(accO[i][0], accO[i][0], cp);
            mul2(accO[i][1], accO[i][1], cp);
            ull* pp = Pd + (tR + 16 * i) * QD_STRIDE + tC * 4;
            ulonglong2 w0; w0.x = pk2(p[0], p[0]); w0.y = pk2(p[1], p[1]);
            ulonglong2 w1; w1.x = pk2(p[2], p[2]); w1.y = pk2(p[3], p[3]);
            *(ulonglong2*)pp       = w0;
            *(ulonglong2*)(pp + 2) = w1;
        }
        __syncthreads();

        // O += P @ V
#pragma unroll 4
        for (int j4 = 0; j4 < 16; j4++) {
            ulonglong2 p01[4], p23[4];
#pragma unroll
            for (int i = 0; i < 4; i++) {
                const ull* pp = Pd + (tR + 16 * i) * QD_STRIDE + j4 * 4;
                p01[i] = *(const ulonglong2*)pp;
                p23[i] = *(const ulonglong2*)(pp + 2);
            }
            ulonglong2 v0 = *(const ulonglong2*)(Vs + (j4 * 4 + 0) * KT_STRIDE + tC * 4);
            ulonglong2 v1 = *(const ulonglong2*)(Vs + (j4 * 4 + 1) * KT_STRIDE + tC * 4);
            ulonglong2 v2 = *(const ulonglong2*)(Vs + (j4 * 4 + 2) * KT_STRIDE + tC * 4);
            ulonglong2 v3 = *(const ulonglong2*)(Vs + (j4 * 4 + 3) * KT_STRIDE + tC * 4);
#pragma unroll
            for (int i = 0; i < 4; i++) {
                fma2(accO[i][0], p01[i].x, v0.x); fma2(accO[i][1], p01[i].x, v0.y);
                fma2(accO[i][0], p01[i].y, v1.x); fma2(accO[i][1], p01[i].y, v1.y);
                fma2(accO[i][0], p23[i].x, v2.x); fma2(accO[i][1], p23[i].x, v2.y);
                fma2(accO[i][0], p23[i].y, v3.x); fma2(accO[i][1], p23[i].y, v3.y);
            }
        }
    }

    // finalize
#pragma unroll
    for (int i = 0; i < 4; i++) {
        const float inv_l = 1.0f / l[i];
        const int grow = q0 + tR + 16 * i;
        float2 f0 = upk(accO[i][0]);
        float2 f1 = upk(accO[i][1]);
        float4 r;
        r.x = f0.x * inv_l; r.y = f0.y * inv_l;
        r.z = f1.x * inv_l; r.w = f1.y * inv_l;
        *(float4*)(y + (size_t)grow * C_DIM + h * HS + tC * 4) = r;
    }
}

// ---------------------------------------------------------------------------
extern "C" void kernel_launch(void* const* d_in, const int* in_sizes, int n_in,
                              void* d_out, int out_size)
{
    const float* x      = (const float*)d_in[0];   // [1,1024,768]
    const float* W_attn = (const float*)d_in[1];   // [768, 2304]
    const float* b_attn = (const float*)d_in[2];   // [2304]
    const float* W_proj = (const float*)d_in[3];   // [768, 768]
    const float* b_proj = (const float*)d_in[4];   // [768]
    float* out = (float*)d_out;                    // [1,1024,768]

    float *qkv, *y;
    cudaGetSymbolAddress((void**)&qkv, g_qkv);
    cudaGetSymbolAddress((void**)&y, g_y);

    const int smem_qkv  = (128 + 128) * 40 * 4 * 2;   // 81920
    const int smem_proj = (64 + 128) * 40 * 4 * 2;    // 61440
    cudaFuncSetAttribute(gemm_mma<128, 128>,
                         cudaFuncAttributeMaxDynamicSharedMemorySize, smem_qkv);
    cudaFuncSetAttribute(gemm_mma<64, 128>,
                         cudaFuncAttributeMaxDynamicSharedMemorySize, smem_proj);
    cudaFuncSetAttribute(attn_kernel,
                         cudaFuncAttributeMaxDynamicSharedMemorySize, SM_ATTN_TOTAL);

    // 1) qkv = x @ W_attn + b_attn   [1024, 2304]
    {
        dim3 grid(C3 / 128, T_SEQ / 128);   // (18, 8) = 144
        gemm_mma<128, 128><<<grid, 256, smem_qkv>>>(T_SEQ, C3, C_DIM,
                                                    x, W_attn, b_attn, qkv);
    }
    // 2) causal flash attention -> y [1024, 768]
    {
        attn_kernel<<<(T_SEQ / 64) * NH, 256, SM_ATTN_TOTAL>>>(qkv, y);
    }
    // 3) out = y @ W_proj + b_proj   [1024, 768]
    {
        dim3 grid(C_DIM / 128, T_SEQ / 64);  // (6, 16) = 96
        gemm_mma<64, 128><<<grid, 256, smem_proj>>>(T_SEQ, C_DIM, C_DIM,
                                                    y, W_proj, b_proj, out);
    }
}

// round 5
// speedup vs baseline: 2.8975x; 1.4860x over previous
#include <cuda_runtime.h>
#include <cstdint>
#include <math.h>

#define T_SEQ 1024
#define C_DIM 768
#define NH    12
#define HS    64
#define C3    (3 * C_DIM)   // 2304

typedef unsigned long long ull;

// Scratch (allocation-free rule: __device__ globals)
__device__ float g_qkv[T_SEQ * C3];      // [T, 3C]
__device__ float g_y[T_SEQ * C_DIM];     // [T, C] attention output

// ---------------------------------------------------------------------------
// tf32 mma.sync helpers (baseline PTX, compiles at compute_100)
// ---------------------------------------------------------------------------
__device__ __forceinline__ uint32_t to_tf32(float f) {
    uint32_t u; asm("cvt.rna.tf32.f32 %0, %1;" : "=r"(u) : "f"(f)); return u;
}
__device__ __forceinline__ void mma_tf32(float* c, const uint32_t* a, const uint32_t* b) {
    asm volatile(
        "mma.sync.aligned.m16n8k8.row.col.f32.tf32.tf32.f32 "
        "{%0,%1,%2,%3},{%4,%5,%6,%7},{%8,%9},{%0,%1,%2,%3};"
        : "+f"(c[0]), "+f"(c[1]), "+f"(c[2]), "+f"(c[3])
        : "r"(a[0]), "r"(a[1]), "r"(a[2]), "r"(a[3]), "r"(b[0]), "r"(b[1]));
}
__device__ __forceinline__ float ex2(float x) {
    float r; asm("ex2.approx.f32 %0, %1;" : "=f"(r) : "f"(x)); return r;
}

extern __shared__ char sm_dyn[];

// ---------------------------------------------------------------------------
// tf32 tensor-core GEMM: C[M,N] = A[M,K] @ B[K,N] + bias[N]  (row-major fp32)
// (unchanged from round 4: 59us qkv / ~30us proj)
// ---------------------------------------------------------------------------
template<int BM, int BN>
__global__ __launch_bounds__(256)
void gemm_mma(int M, int N, int K,
              const float* __restrict__ A,
              const float* __restrict__ B,
              const float* __restrict__ bias,
              float* __restrict__ C)
{
    constexpr int BK = 32;
    constexpr int RS = 40;
    constexpr int WM = BM / 2;
    constexpr int WN = BN / 4;
    constexpr int MT = WM / 16;
    constexpr int NT = WN / 8;
    constexpr int UA = (BM * 4) / 256;
    constexpr int UB = (BN * 4) / 256;
    static_assert(UA >= 1 && UB >= 1, "tile too small");

    float* S = (float*)sm_dyn;
    float* AsB[2] = { S,           S + (BM + BN) * RS };
    float* BsB[2] = { S + BM * RS, S + (BM + BN) * RS + BM * RS };

    const int tid = threadIdx.x;
    const int wid = tid >> 5;
    const int lane = tid & 31;
    const int gid = lane >> 2;
    const int tg  = lane & 3;
    const int wm = wid >> 2;
    const int wn = wid & 3;
    const int m0 = blockIdx.y * BM;
    const int n0 = blockIdx.x * BN;

    float acc[MT][NT][4];
#pragma unroll
    for (int i = 0; i < MT; i++)
#pragma unroll
        for (int j = 0; j < NT; j++)
#pragma unroll
            for (int v = 0; v < 4; v++) acc[i][j][v] = 0.0f;

    float4 ra[UA][2];
    float  rb[UB][8];
    const int nk = K / BK;

    auto load_regs = [&](int kc) {
#pragma unroll
        for (int u = 0; u < UA; u++) {
            const int idx = tid + 256 * u;
            const int row = idx >> 2;
            const int s   = idx & 3;
            const float* p = A + (size_t)(m0 + row) * K + kc + s * 8;
            ra[u][0] = *(const float4*)p;
            ra[u][1] = *(const float4*)(p + 4);
        }
#pragma unroll
        for (int u = 0; u < UB; u++) {
            const int idx = tid + 256 * u;
            const int n   = idx % BN;
            const int s   = idx / BN;
            const float* p = B + (size_t)(kc + s * 8) * N + n0 + n;
#pragma unroll
            for (int kk = 0; kk < 8; kk++) rb[u][kk] = p[(size_t)kk * N];
        }
    };
    auto store_smem = [&](int buf) {
        float* As = AsB[buf];
        float* Bs = BsB[buf];
#pragma unroll
        for (int u = 0; u < UA; u++) {
            const int idx = tid + 256 * u;
            const int row = idx >> 2;
            const int s   = idx & 3;
            uint4 w0, w1;
            w0.x = to_tf32(ra[u][0].x); w0.y = to_tf32(ra[u][1].x);
            w0.z = to_tf32(ra[u][0].y); w0.w = to_tf32(ra[u][1].y);
            w1.x = to_tf32(ra[u][0].z); w1.y = to_tf32(ra[u][1].z);
            w1.z = to_tf32(ra[u][0].w); w1.w = to_tf32(ra[u][1].w);
            uint32_t* p = (uint32_t*)&As[row * RS + s * 8];
            *(uint4*)p       = w0;
            *(uint4*)(p + 4) = w1;
        }
#pragma unroll
        for (int u = 0; u < UB; u++) {
            const int idx = tid + 256 * u;
            const int n   = idx % BN;
            const int s   = idx / BN;
            uint4 w0, w1;
            w0.x = to_tf32(rb[u][0]); w0.y = to_tf32(rb[u][4]);
            w0.z = to_tf32(rb[u][1]); w0.w = to_tf32(rb[u][5]);
            w1.x = to_tf32(rb[u][2]); w1.y = to_tf32(rb[u][6]);
            w1.z = to_tf32(rb[u][3]); w1.w = to_tf32(rb[u][7]);
            uint32_t* p = (uint32_t*)&Bs[n * RS + s * 8];
            *(uint4*)p       = w0;
            *(uint4*)(p + 4) = w1;
        }
    };

    load_regs(0);
    store_smem(0);
    __syncthreads();

    for (int i = 0; i < nk; i++) {
        if (i + 1 < nk) load_regs((i + 1) * BK);

        const int buf = i & 1;
        const float* As = AsB[buf];
        const float* Bs = BsB[buf];
#pragma unroll
        for (int s = 0; s < 4; s++) {
            uint32_t af[MT][4], bf[NT][2];
#pragma unroll
            for (int mt = 0; mt < MT; mt++) {
                const int row = wm * WM + mt * 16 + gid;
                const uint32_t* lo = (const uint32_t*)&As[row * RS + s * 8 + tg * 2];
                const uint32_t* hi = (const uint32_t*)&As[(row + 8) * RS + s * 8 + tg * 2];
                af[mt][0] = lo[0]; af[mt][2] = lo[1];
                af[mt][1] = hi[0]; af[mt][3] = hi[1];
            }
#pragma unroll
            for (int nt = 0; nt < NT; nt++) {
                const int n = wn * WN + nt * 8 + gid;
                const uint32_t* bp = (const uint32_t*)&Bs[n * RS + s * 8 + tg * 2];
                bf[nt][0] = bp[0]; bf[nt][1] = bp[1];
            }
#pragma unroll
            for (int mt = 0; mt < MT; mt++)
#pragma unroll
                for (int nt = 0; nt < NT; nt++)
                    mma_tf32(acc[mt][nt], af[mt], bf[nt]);
        }

        if (i + 1 < nk) {
            store_smem(buf ^ 1);
            __syncthreads();
        }
    }

#pragma unroll
    for (int mt = 0; mt < MT; mt++) {
        const int row = m0 + wm * WM + mt * 16 + gid;
#pragma unroll
        for (int nt = 0; nt < NT; nt++) {
            const int col = n0 + wn * WN + nt * 8 + 2 * tg;
            const float b0 = bias[col], b1 = bias[col + 1];
            float2 r0, r1;
            r0.x = acc[mt][nt][0] + b0; r0.y = acc[mt][nt][1] + b1;
            r1.x = acc[mt][nt][2] + b0; r1.y = acc[mt][nt][3] + b1;
            *(float2*)(C + (size_t)row * N + col)       = r0;
            *(float2*)(C + (size_t)(row + 8) * N + col) = r1;
        }
    }
}

// ---------------------------------------------------------------------------
// Tensor-core flash attention (tf32 mma, fp32 softmax/accum), causal.
// Block = (64-row q-tile, head), 128 threads = 4 warps.
// Warp w owns q-rows [w*16, w*16+16) x all 64 keys of each key tile.
// SMEM fragment-pair panels (RS=40, 32 k-cols each, pairs (c, c+4)):
//   Qs[2]: q rows x dims     (A for S-mma)
//   Ks[2]: key rows x dims   (B for S-mma, natural layout)
//   Vt[2]: dim rows x keys   (B for PV-mma, transposed at load)
//   Ps[2]: q rows x keys     (A for PV-mma, per-warp private rows)
// ---------------------------------------------------------------------------
#define PSZ (64 * 40)              // floats per panel
#define SM_ATTN_TOTAL (8 * PSZ * 4)   // 81920 B

__device__ __forceinline__ int pair_slot(int k) {  // k in [0,32)
    const int s = k >> 3, t = k & 7;
    return s * 8 + (t < 4 ? 2 * t : 2 * (t - 4) + 1);
}

__global__ __launch_bounds__(128, 2)
void attn_kernel(const float* __restrict__ qkv, float* __restrict__ y)
{
    float* S  = (float*)sm_dyn;
    float* Qs = S;                 // 2 panels
    float* Ks = S + 2 * PSZ;
    float* Vt = S + 4 * PSZ;
    float* Ps = S + 6 * PSZ;

    const int tid  = threadIdx.x;
    const int w    = tid >> 5;
    const int lane = tid & 31;
    const int gid  = lane >> 2;    // 0..7
    const int tg   = lane & 3;     // 0..3
    const int b    = blockIdx.x;
    const int qt   = 15 - (b / NH);
    const int h    = b % NH;
    const int q0   = qt * 64;

    // ---- load Q tile into fragment-pair panels (tf32)
#pragma unroll
    for (int it = 0; it < 8; it++) {
        const int lin = tid + 128 * it;
        const int r   = lin >> 4;            // 0..63
        const int c4  = (lin & 15) * 4;      // 0..60
        float4 v = *(const float4*)(qkv + (size_t)(q0 + r) * C3 + h * HS + c4);
        const int panel = c4 >> 5;
        const int kk    = c4 & 31;           // multiple of 4 -> t in {0,4}
        const int base  = (kk >> 3) * 8 + ((kk & 7) ? 1 : 0);
        float* p = Qs + panel * PSZ + r * 40 + base;
        p[0] = __uint_as_float(to_tf32(v.x));
        p[2] = __uint_as_float(to_tf32(v.y));
        p[4] = __uint_as_float(to_tf32(v.z));
        p[6] = __uint_as_float(to_tf32(v.w));
    }

    float accO[8][4];
#pragma unroll
    for (int nt = 0; nt < 8; nt++)
#pragma unroll
        for (int v = 0; v < 4; v++) accO[nt][v] = 0.0f;
    float m0r = -1e30f, m1r = -1e30f, l0 = 0.0f, l1 = 0.0f;

    const float SC = 0.125f * 1.4426950408889634f;   // scale * 1/ln2
    const int rl0 = w * 16 + gid;       // local q row (low)
    const int rl1 = rl0 + 8;

    for (int kt = 0; kt <= qt; kt++) {
        const int j0 = kt * 64;
        __syncthreads();   // prior-iteration readers of Ks/Vt done

        // ---- load K tile (natural [key][dim] pair layout)
#pragma unroll
        for (int it = 0; it < 8; it++) {
            const int lin = tid + 128 * it;
            const int r   = lin >> 4;
            const int c4  = (lin & 15) * 4;
            float4 v = *(const float4*)(qkv + (size_t)(j0 + r) * C3 + C_DIM + h * HS + c4);
            const int panel = c4 >> 5;
            const int kk    = c4 & 31;
            const int base  = (kk >> 3) * 8 + ((kk & 7) ? 1 : 0);
            float* p = Ks + panel * PSZ + r * 40 + base;
            p[0] = __uint_as_float(to_tf32(v.x));
            p[2] = __uint_as_float(to_tf32(v.y));
            p[4] = __uint_as_float(to_tf32(v.z));
            p[6] = __uint_as_float(to_tf32(v.w));
        }
        // ---- load V tile transposed: Vt[dim][key] pair layout over keys
#pragma unroll
        for (int it = 0; it < 8; it++) {
            const int lin = tid + 128 * it;
            const int j   = lin & 63;            // key
            const int c4  = (lin >> 6) * 4;      // dim base
            float4 v = *(const float4*)(qkv + (size_t)(j0 + j) * C3 + 2 * C_DIM + h * HS + c4);
            const int panel = j >> 5;
            const int slot  = pair_slot(j & 31);
            float* p = Vt + panel * PSZ + c4 * 40 + slot;
            p[0 * 40] = __uint_as_float(to_tf32(v.x));
            p[1 * 40] = __uint_as_float(to_tf32(v.y));
            p[2 * 40] = __uint_as_float(to_tf32(v.z));
            p[3 * 40] = __uint_as_float(to_tf32(v.w));
        }
        __syncthreads();

        // ---- S = Q K^T  (per warp: 16 rows x 64 keys)
        float accS[8][4];
#pragma unroll
        for (int nt = 0; nt < 8; nt++)
#pragma unroll
            for (int v = 0; v < 4; v++) accS[nt][v] = 0.0f;

#pragma unroll
        for (int pc = 0; pc < 2; pc++) {
            const float* Qp = Qs + pc * PSZ;
            const float* Kp = Ks + pc * PSZ;
#pragma unroll
            for (int s = 0; s < 4; s++) {
                uint32_t af[4];
                const uint32_t* lo = (const uint32_t*)&Qp[rl0 * 40 + s * 8 + tg * 2];
                const uint32_t* hi = (const uint32_t*)&Qp[(rl0 + 8) * 40 + s * 8 + tg * 2];
                af[0] = lo[0]; af[2] = lo[1];
                af[1] = hi[0]; af[3] = hi[1];
#pragma unroll
                for (int nt = 0; nt < 8; nt++) {
                    uint32_t bf[2];
                    const uint32_t* bp = (const uint32_t*)&Kp[(nt * 8 + gid) * 40 + s * 8 + tg * 2];
                    bf[0] = bp[0]; bf[1] = bp[1];
                    mma_tf32(accS[nt], af, bf);
                }
            }
        }

        // ---- scale (log2 domain) + causal mask
        const bool diag = (kt == qt);
#pragma unroll
        for (int nt = 0; nt < 8; nt++) {
            const int c0 = nt * 8 + 2 * tg;
#pragma unroll
            for (int v = 0; v < 4; v++) accS[nt][v] *= SC;
            if (diag) {
                if (c0     > rl0) accS[nt][0] = -1e30f;
                if (c0 + 1 > rl0) accS[nt][1] = -1e30f;
                if (c0     > rl1) accS[nt][2] = -1e30f;
                if (c0 + 1 > rl1) accS[nt][3] = -1e30f;
            }
        }

        // ---- online softmax (rows rl0, rl1; quad reduction over tg)
        float mx0 = -1e30f, mx1 = -1e30f;
#pragma unroll
        for (int nt = 0; nt < 8; nt++) {
            mx0 = fmaxf(mx0, fmaxf(accS[nt][0], accS[nt][1]));
            mx1 = fmaxf(mx1, fmaxf(accS[nt][2], accS[nt][3]));
        }
        mx0 = fmaxf(mx0, __shfl_xor_sync(0xffffffffu, mx0, 1));
        mx0 = fmaxf(mx0, __shfl_xor_sync(0xffffffffu, mx0, 2));
        mx1 = fmaxf(mx1, __shfl_xor_sync(0xffffffffu, mx1, 1));
        mx1 = fmaxf(mx1, __shfl_xor_sync(0xffffffffu, mx1, 2));
        const float mn0 = fmaxf(m0r, mx0);
        const float mn1 = fmaxf(m1r, mx1);
        const float cr0 = ex2(m0r - mn0);
        const float cr1 = ex2(m1r - mn1);
        m0r = mn0; m1r = mn1;

        float ps0 = 0.0f, ps1 = 0.0f;
#pragma unroll
        for (int nt = 0; nt < 8; nt++) {
            accS[nt][0] = ex2(accS[nt][0] - mn0);
            accS[nt][1] = ex2(accS[nt][1] - mn0);
            accS[nt][2] = ex2(accS[nt][2] - mn1);
            accS[nt][3] = ex2(accS[nt][3] - mn1);
            ps0 += accS[nt][0] + accS[nt][1];
            ps1 += accS[nt][2] + accS[nt][3];
        }
        ps0 += __shfl_xor_sync(0xffffffffu, ps0, 1);
        ps0 += __shfl_xor_sync(0xffffffffu, ps0, 2);
        ps1 += __shfl_xor_sync(0xffffffffu, ps1, 1);
        ps1 += __shfl_xor_sync(0xffffffffu, ps1, 2);
        l0 = l0 * cr0 + ps0;
        l1 = l1 * cr1 + ps1;
#pragma unroll
        for (int nt = 0; nt < 8; nt++) {
            accO[nt][0] *= cr0; accO[nt][1] *= cr0;
            accO[nt][2] *= cr1; accO[nt][3] *= cr1;
        }

        // ---- store P (tf32) into per-warp Ps rows
        __syncwarp();
#pragma unroll
        for (int nt = 0; nt < 8; nt++) {
            const int c0   = nt * 8 + 2 * tg;
            const int pan0 = c0 >> 5;
            const int sl0  = pair_slot(c0 & 31);
            const int sl1  = pair_slot((c0 + 1) & 31);   // same panel (c0+1 < next 32)
            float* base0 = Ps + pan0 * PSZ;
            base0[rl0 * 40 + sl0] = __uint_as_float(to_tf32(accS[nt][0]));
            base0[rl0 * 40 + sl1] = __uint_as_float(to_tf32(accS[nt][1]));
            base0[rl1 * 40 + sl0] = __uint_as_float(to_tf32(accS[nt][2]));
            base0[rl1 * 40 + sl1] = __uint_as_float(to_tf32(accS[nt][3]));
        }
        __syncwarp();

        // ---- O += P @ V
#pragma unroll
        for (int pc = 0; pc < 2; pc++) {
            const float* Pp = Ps + pc * PSZ;
            const float* Vp = Vt + pc * PSZ;
#pragma unroll
            for (int s = 0; s < 4; s++) {
                uint32_t af[4];
                const uint32_t* lo = (const uint32_t*)&Pp[rl0 * 40 + s * 8 + tg * 2];
                const uint32_t* hi = (const uint32_t*)&Pp[(rl0 + 8) * 40 + s * 8 + tg * 2];
                af[0] = lo[0]; af[2] = lo[1];
                af[1] = hi[0]; af[3] = hi[1];
#pragma unroll
                for (int nt = 0; nt < 8; nt++) {
                    uint32_t bf[2];
                    const uint32_t* bp = (const uint32_t*)&Vp[(nt * 8 + gid) * 40 + s * 8 + tg * 2];
                    bf[0] = bp[0]; bf[1] = bp[1];
                    mma_tf32(accO[nt], af, bf);
                }
            }
        }
    }

    // ---- finalize: divide by l, write y
    const float inv0 = 1.0f / l0;
    const float inv1 = 1.0f / l1;
    const int gr0 = q0 + rl0;
    const int gr1 = q0 + rl1;
#pragma unroll
    for (int nt = 0; nt < 8; nt++) {
        const int col = h * HS + nt * 8 + 2 * tg;
        float2 r0, r1;
        r0.x = accO[nt][0] * inv0; r0.y = accO[nt][1] * inv0;
        r1.x = accO[nt][2] * inv1; r1.y = accO[nt][3] * inv1;
        *(float2*)(y + (size_t)gr0 * C_DIM + col) = r0;
        *(float2*)(y + (size_t)gr1 * C_DIM + col) = r1;
    }
}

// ---------------------------------------------------------------------------
extern "C" void kernel_launch(void* const* d_in, const int* in_sizes, int n_in,
                              void* d_out, int out_size)
{
    const float* x      = (const float*)d_in[0];   // [1,1024,768]
    const float* W_attn = (const float*)d_in[1];   // [768, 2304]
    const float* b_attn = (const float*)d_in[2];   // [2304]
    const float* W_proj = (const float*)d_in[3];   // [768, 768]
    const float* b_proj = (const float*)d_in[4];   // [768]
    float* out = (float*)d_out;                    // [1,1024,768]

    float *qkv, *y;
    cudaGetSymbolAddress((void**)&qkv, g_qkv);
    cudaGetSymbolAddress((void**)&y, g_y);

    const int smem_qkv  = (128 + 128) * 40 * 4 * 2;   // 81920
    const int smem_proj = (64 + 128) * 40 * 4 * 2;    // 61440
    cudaFuncSetAttribute(gemm_mma<128, 128>,
                         cudaFuncAttributeMaxDynamicSharedMemorySize, smem_qkv);
    cudaFuncSetAttribute(gemm_mma<64, 128>,
                         cudaFuncAttributeMaxDynamicSharedMemorySize, smem_proj);
    cudaFuncSetAttribute(attn_kernel,
                         cudaFuncAttributeMaxDynamicSharedMemorySize, SM_ATTN_TOTAL);

    // 1) qkv = x @ W_attn + b_attn   [1024, 2304]
    {
        dim3 grid(C3 / 128, T_SEQ / 128);   // (18, 8) = 144
        gemm_mma<128, 128><<<grid, 256, smem_qkv>>>(T_SEQ, C3, C_DIM,
                                                    x, W_attn, b_attn, qkv);
    }
    // 2) causal flash attention (tensor cores) -> y [1024, 768]
    {
        attn_kernel<<<(T_SEQ / 64) * NH, 128, SM_ATTN_TOTAL>>>(qkv, y);
    }
    // 3) out = y @ W_proj + b_proj   [1024, 768]
    {
        dim3 grid(C_DIM / 128, T_SEQ / 64);  // (6, 16) = 96
        gemm_mma<64, 128><<<grid, 256, smem_proj>>>(T_SEQ, C_DIM, C_DIM,
                                                    y, W_proj, b_proj, out);
    }
}

// round 6
// speedup vs baseline: 3.5414x; 1.2222x over previous
#include <cuda_runtime.h>
#include <cstdint>
#include <math.h>

#define T_SEQ 1024
#define C_DIM 768
#define NH    12
#define HS    64
#define C3    (3 * C_DIM)   // 2304

// Scratch (allocation-free rule: __device__ globals)
__device__ float g_qkv[T_SEQ * C3];          // [T, 3C] fp32
__device__ float g_y[T_SEQ * C_DIM];         // [T, C] attention out, PERMUTED tf32
__device__ float g_xp[T_SEQ * C_DIM];        // x permuted tf32
__device__ float g_wattn[C3 * C_DIM];        // W_attn^T permuted tf32  [2304][768]
__device__ float g_wproj[C_DIM * C_DIM];     // W_proj^T permuted tf32  [768][768]

// ---------------------------------------------------------------------------
// helpers
// ---------------------------------------------------------------------------
__device__ __forceinline__ uint32_t to_tf32(float f) {
    uint32_t u; asm("cvt.rna.tf32.f32 %0, %1;" : "=r"(u) : "f"(f)); return u;
}
__device__ __forceinline__ void mma_tf32(float* c, const uint32_t* a, const uint32_t* b) {
    asm volatile(
        "mma.sync.aligned.m16n8k8.row.col.f32.tf32.tf32.f32 "
        "{%0,%1,%2,%3},{%4,%5,%6,%7},{%8,%9},{%0,%1,%2,%3};"
        : "+f"(c[0]), "+f"(c[1]), "+f"(c[2]), "+f"(c[3])
        : "r"(a[0]), "r"(a[1]), "r"(a[2]), "r"(a[3]), "r"(b[0]), "r"(b[1]));
}
__device__ __forceinline__ float ex2(float x) {
    float r; asm("ex2.approx.f32 %0, %1;" : "=f"(r) : "f"(x)); return r;
}
__device__ __forceinline__ uint32_t smem_u32(const void* p) {
    uint32_t a;
    asm("{ .reg .u64 t; cvta.to.shared.u64 t, %1; cvt.u32.u64 %0, t; }" : "=r"(a) : "l"(p));
    return a;
}
__device__ __forceinline__ void cp16(uint32_t s, const void* g) {
    asm volatile("cp.async.cg.shared.global [%0], [%1], 16;" :: "r"(s), "l"(g) : "memory");
}
#define CP_COMMIT() asm volatile("cp.async.commit_group;" ::: "memory")
#define CP_WAIT1()  asm volatile("cp.async.wait_group 1;" ::: "memory")
#define CP_WAIT0()  asm volatile("cp.async.wait_group 0;" ::: "memory")

// slot g holds column (g & ~7) | sigma(g & 7); sigma(u) = (u>>1) + ((u&1)<<2)
__device__ __forceinline__ int sigma8(int u) { return (u >> 1) + ((u & 1) << 2); }

extern __shared__ char sm_dyn[];

// ---------------------------------------------------------------------------
// Pre-pass 1: row-wise permute + tf32 convert (for x)
// out[row][g] = tf32(in[row][(g&~7)|sigma(g&7)])
// ---------------------------------------------------------------------------
__global__ void permute_rows(const float* __restrict__ in, float* __restrict__ out, int total)
{
    const int i = blockIdx.x * 256 + threadIdx.x;
    if (i >= total) return;
    const int g = i & (C_DIM - 1) & 7;       // careful: need k within row
    const int row = i / C_DIM;
    const int k = i - row * C_DIM;
    const int src = (k & ~7) | sigma8(k & 7);
    out[i] = __uint_as_float(to_tf32(in[row * C_DIM + src]));
    (void)g;
}

// ---------------------------------------------------------------------------
// Pre-pass 2: transpose + permute + tf32 convert for weights
// in: [K][N] row-major.  out: [N][K], out[n][g] = tf32(in[(g&~7)|sigma(g&7)][n])
// ---------------------------------------------------------------------------
__global__ void transpose_permute(const float* __restrict__ in, float* __restrict__ out,
                                  int K, int N)
{
    __shared__ float tile[32][33];
    const int tx = threadIdx.x;       // 0..31
    const int ty = threadIdx.y;       // 0..7
    const int n0 = blockIdx.x * 32;
    const int k0 = blockIdx.y * 32;
#pragma unroll
    for (int j = 0; j < 4; j++)
        tile[ty + 8 * j][tx] = in[(size_t)(k0 + ty + 8 * j) * N + n0 + tx];
    __syncthreads();
    const int src = (tx & ~7) | sigma8(tx & 7);
#pragma unroll
    for (int j = 0; j < 4; j++)
        out[(size_t)(n0 + ty + 8 * j) * K + k0 + tx] =
            __uint_as_float(to_tf32(tile[src][ty + 8 * j]));
}

// ---------------------------------------------------------------------------
// cp.async tf32 tensor-core GEMM: C[M,N] = A'[M,K] @ B'[N,K]^T + bias[N]
// A', B' pre-converted tf32 in fragment-pair slot order. BK=32, 3 stages,
// 256 threads = 8 warps (2 x 4), one __syncthreads per K-iteration.
// ---------------------------------------------------------------------------
template<int BM, int BN>
__global__ __launch_bounds__(256)
void gemm_cp(int M, int N, int K,
             const float* __restrict__ Ap,
             const float* __restrict__ Bp,
             const float* __restrict__ bias,
             float* __restrict__ C)
{
    constexpr int BK  = 32;
    constexpr int RS  = 40;
    constexpr int STG = 3;
    constexpr int UA  = BM / 32;       // A 16B chunks per thread per stage
    constexpr int UB  = BN / 32;
    constexpr int SSA = BM * RS;       // floats
    constexpr int SSB = BN * RS;
    constexpr int WM  = BM / 2;
    constexpr int WN  = BN / 4;
    constexpr int MT  = WM / 16;
    constexpr int NT  = WN / 8;

    float* S = (float*)sm_dyn;
    const uint32_t sbase = smem_u32(S);

    const int tid  = threadIdx.x;
    const int wid  = tid >> 5;
    const int lane = tid & 31;
    const int gid  = lane >> 2;
    const int tg   = lane & 3;
    const int wm   = wid >> 2;
    const int wn   = wid & 3;
    const int m0   = blockIdx.y * BM;
    const int n0   = blockIdx.x * BN;

    const int arow = tid >> 3;          // A chunk row base (per u: +32 rows? no, +256/8)
    const int ach  = tid & 7;

    float acc[MT][NT][4];
#pragma unroll
    for (int i = 0; i < MT; i++)
#pragma unroll
        for (int j = 0; j < NT; j++)
#pragma unroll
            for (int v = 0; v < 4; v++) acc[i][j][v] = 0.0f;

    auto issue_stage = [&](int i) {
        const int st = i % STG;
        const int kc = i * BK;
        const uint32_t ab = sbase + st * (SSA + SSB) * 4;
#pragma unroll
        for (int u = 0; u < UA; u++) {
            const int row = arow + u * 32;
            cp16(ab + (row * RS + ach * 4) * 4,
                 Ap + (size_t)(m0 + row) * K + kc + ach * 4);
        }
        const uint32_t bb = ab + SSA * 4;
#pragma unroll
        for (int u = 0; u < UB; u++) {
            const int row = arow + u * 32;
            cp16(bb + (row * RS + ach * 4) * 4,
                 Bp + (size_t)(n0 + row) * K + kc + ach * 4);
        }
        CP_COMMIT();
    };

    issue_stage(0);
    issue_stage(1);

    const int nk = K / BK;
    for (int i = 0; i < nk; i++) {
        if (i + 1 < nk) CP_WAIT1(); else CP_WAIT0();
        __syncthreads();

        const int st = i % STG;
        const float* Aq = S + st * (SSA + SSB);
        const float* Bq = Aq + SSA;

#pragma unroll
        for (int s = 0; s < 4; s++) {
            uint32_t af[MT][4], bf[NT][2];
#pragma unroll
            for (int mt = 0; mt < MT; mt++) {
                const int row = wm * WM + mt * 16 + gid;
                const uint32_t* lo = (const uint32_t*)&Aq[row * RS + s * 8 + tg * 2];
                const uint32_t* hi = (const uint32_t*)&Aq[(row + 8) * RS + s * 8 + tg * 2];
                af[mt][0] = lo[0]; af[mt][2] = lo[1];
                af[mt][1] = hi[0]; af[mt][3] = hi[1];
            }
#pragma unroll
            for (int nt = 0; nt < NT; nt++) {
                const int n = wn * WN + nt * 8 + gid;
                const uint32_t* bp = (const uint32_t*)&Bq[n * RS + s * 8 + tg * 2];
                bf[nt][0] = bp[0]; bf[nt][1] = bp[1];
            }
#pragma unroll
            for (int mt = 0; mt < MT; mt++)
#pragma unroll
                for (int nt = 0; nt < NT; nt++)
                    mma_tf32(acc[mt][nt], af[mt], bf[nt]);
        }

        if (i + 2 < nk) issue_stage(i + 2);   // target buf consumed at iter i-1
    }

    // epilogue: bias + store fp32
#pragma unroll
    for (int mt = 0; mt < MT; mt++) {
        const int row = m0 + wm * WM + mt * 16 + gid;
#pragma unroll
        for (int nt = 0; nt < NT; nt++) {
            const int col = n0 + wn * WN + nt * 8 + 2 * tg;
            const float b0 = bias[col], b1 = bias[col + 1];
            float2 r0, r1;
            r0.x = acc[mt][nt][0] + b0; r0.y = acc[mt][nt][1] + b1;
            r1.x = acc[mt][nt][2] + b0; r1.y = acc[mt][nt][3] + b1;
            *(float2*)(C + (size_t)row * N + col)       = r0;
            *(float2*)(C + (size_t)(row + 8) * N + col) = r1;
        }
    }
}

// ---------------------------------------------------------------------------
// Tensor-core flash attention (tf32 mma, fp32 softmax/accum), causal.
// Same as round 5; finalize now writes y in PERMUTED tf32 layout for proj GEMM.
// ---------------------------------------------------------------------------
#define PSZ (64 * 40)
#define SM_ATTN_TOTAL (8 * PSZ * 4)   // 81920 B

__device__ __forceinline__ int pair_slot(int k) {
    const int s = k >> 3, t = k & 7;
    return s * 8 + (t < 4 ? 2 * t : 2 * (t - 4) + 1);
}

__global__ __launch_bounds__(128, 2)
void attn_kernel(const float* __restrict__ qkv, float* __restrict__ yp)
{
    float* S  = (float*)sm_dyn;
    float* Qs = S;
    float* Ks = S + 2 * PSZ;
    float* Vt = S + 4 * PSZ;
    float* Ps = S + 6 * PSZ;

    const int tid  = threadIdx.x;
    const int w    = tid >> 5;
    const int lane = tid & 31;
    const int gid  = lane >> 2;
    const int tg   = lane & 3;
    const int b    = blockIdx.x;
    const int qt   = 15 - (b / NH);
    const int h    = b % NH;
    const int q0   = qt * 64;

#pragma unroll
    for (int it = 0; it < 8; it++) {
        const int lin = tid + 128 * it;
        const int r   = lin >> 4;
        const int c4  = (lin & 15) * 4;
        float4 v = *(const float4*)(qkv + (size_t)(q0 + r) * C3 + h * HS + c4);
        const int panel = c4 >> 5;
        const int kk    = c4 & 31;
        const int base  = (kk >> 3) * 8 + ((kk & 7) ? 1 : 0);
        float* p = Qs + panel * PSZ + r * 40 + base;
        p[0] = __uint_as_float(to_tf32(v.x));
        p[2] = __uint_as_float(to_tf32(v.y));
        p[4] = __uint_as_float(to_tf32(v.z));
        p[6] = __uint_as_float(to_tf32(v.w));
    }

    float accO[8][4];
#pragma unroll
    for (int nt = 0; nt < 8; nt++)
#pragma unroll
        for (int v = 0; v < 4; v++) accO[nt][v] = 0.0f;
    float m0r = -1e30f, m1r = -1e30f, l0 = 0.0f, l1 = 0.0f;

    const float SC = 0.125f * 1.4426950408889634f;
    const int rl0 = w * 16 + gid;
    const int rl1 = rl0 + 8;

    for (int kt = 0; kt <= qt; kt++) {
        const int j0 = kt * 64;
        __syncthreads();

#pragma unroll
        for (int it = 0; it < 8; it++) {
            const int lin = tid + 128 * it;
            const int r   = lin >> 4;
            const int c4  = (lin & 15) * 4;
            float4 v = *(const float4*)(qkv + (size_t)(j0 + r) * C3 + C_DIM + h * HS + c4);
            const int panel = c4 >> 5;
            const int kk    = c4 & 31;
            const int base  = (kk >> 3) * 8 + ((kk & 7) ? 1 : 0);
            float* p = Ks + panel * PSZ + r * 40 + base;
            p[0] = __uint_as_float(to_tf32(v.x));
            p[2] = __uint_as_float(to_tf32(v.y));
            p[4] = __uint_as_float(to_tf32(v.z));
            p[6] = __uint_as_float(to_tf32(v.w));
        }
#pragma unroll
        for (int it = 0; it < 8; it++) {
            const int lin = tid + 128 * it;
            const int j   = lin & 63;
            const int c4  = (lin >> 6) * 4;
            float4 v = *(const float4*)(qkv + (size_t)(j0 + j) * C3 + 2 * C_DIM + h * HS + c4);
            const int panel = j >> 5;
            const int slot  = pair_slot(j & 31);
            float* p = Vt + panel * PSZ + c4 * 40 + slot;
            p[0 * 40] = __uint_as_float(to_tf32(v.x));
            p[1 * 40] = __uint_as_float(to_tf32(v.y));
            p[2 * 40] = __uint_as_float(to_tf32(v.z));
            p[3 * 40] = __uint_as_float(to_tf32(v.w));
        }
        __syncthreads();

        float accS[8][4];
#pragma unroll
        for (int nt = 0; nt < 8; nt++)
#pragma unroll
            for (int v = 0; v < 4; v++) accS[nt][v] = 0.0f;

#pragma unroll
        for (int pc = 0; pc < 2; pc++) {
            const float* Qp = Qs + pc * PSZ;
            const float* Kp = Ks + pc * PSZ;
#pragma unroll
            for (int s = 0; s < 4; s++) {
                uint32_t af[4];
                const uint32_t* lo = (const uint32_t*)&Qp[rl0 * 40 + s * 8 + tg * 2];
                const uint32_t* hi = (const uint32_t*)&Qp[(rl0 + 8) * 40 + s * 8 + tg * 2];
                af[0] = lo[0]; af[2] = lo[1];
                af[1] = hi[0]; af[3] = hi[1];
#pragma unroll
                for (int nt = 0; nt < 8; nt++) {
                    uint32_t bf[2];
                    const uint32_t* bp = (const uint32_t*)&Kp[(nt * 8 + gid) * 40 + s * 8 + tg * 2];
                    bf[0] = bp[0]; bf[1] = bp[1];
                    mma_tf32(accS[nt], af, bf);
                }
            }
        }

        const bool diag = (kt == qt);
#pragma unroll
        for (int nt = 0; nt < 8; nt++) {
            const int c0 = nt * 8 + 2 * tg;
#pragma unroll
            for (int v = 0; v < 4; v++) accS[nt][v] *= SC;
            if (diag) {
                if (c0     > rl0) accS[nt][0] = -1e30f;
                if (c0 + 1 > rl0) accS[nt][1] = -1e30f;
                if (c0     > rl1) accS[nt][2] = -1e30f;
                if (c0 + 1 > rl1) accS[nt][3] = -1e30f;
            }
        }

        float mx0 = -1e30f, mx1 = -1e30f;
#pragma unroll
        for (int nt = 0; nt < 8; nt++) {
            mx0 = fmaxf(mx0, fmaxf(accS[nt][0], accS[nt][1]));
            mx1 = fmaxf(mx1, fmaxf(accS[nt][2], accS[nt][3]));
        }
        mx0 = fmaxf(mx0, __shfl_xor_sync(0xffffffffu, mx0, 1));
        mx0 = fmaxf(mx0, __shfl_xor_sync(0xffffffffu, mx0, 2));
        mx1 = fmaxf(mx1, __shfl_xor_sync(0xffffffffu, mx1, 1));
        mx1 = fmaxf(mx1, __shfl_xor_sync(0xffffffffu, mx1, 2));
        const float mn0 = fmaxf(m0r, mx0);
        const float mn1 = fmaxf(m1r, mx1);
        const float cr0 = ex2(m0r - mn0);
        const float cr1 = ex2(m1r - mn1);
        m0r = mn0; m1r = mn1;

        float ps0 = 0.0f, ps1 = 0.0f;
#pragma unroll
        for (int nt = 0; nt < 8; nt++) {
            accS[nt][0] = ex2(accS[nt][0] - mn0);
            accS[nt][1] = ex2(accS[nt][1] - mn0);
            accS[nt][2] = ex2(accS[nt][2] - mn1);
            accS[nt][3] = ex2(accS[nt][3] - mn1);
            ps0 += accS[nt][0] + accS[nt][1];
            ps1 += accS[nt][2] + accS[nt][3];
        }
        ps0 += __shfl_xor_sync(0xffffffffu, ps0, 1);
        ps0 += __shfl_xor_sync(0xffffffffu, ps0, 2);
        ps1 += __shfl_xor_sync(0xffffffffu, ps1, 1);
        ps1 += __shfl_xor_sync(0xffffffffu, ps1, 2);
        l0 = l0 * cr0 + ps0;
        l1 = l1 * cr1 + ps1;
#pragma unroll
        for (int nt = 0; nt < 8; nt++) {
            accO[nt][0] *= cr0; accO[nt][1] *= cr0;
            accO[nt][2] *= cr1; accO[nt][3] *= cr1;
        }

        __syncwarp();
#pragma unroll
        for (int nt = 0; nt < 8; nt++) {
            const int c0   = nt * 8 + 2 * tg;
            const int pan0 = c0 >> 5;
            const int sl0  = pair_slot(c0 & 31);
            const int sl1  = pair_slot((c0 + 1) & 31);
            float* base0 = Ps + pan0 * PSZ;
            base0[rl0 * 40 + sl0] = __uint_as_float(to_tf32(accS[nt][0]));
            base0[rl0 * 40 + sl1] = __uint_as_float(to_tf32(accS[nt][1]));
            base0[rl1 * 40 + sl0] = __uint_as_float(to_tf32(accS[nt][2]));
            base0[rl1 * 40 + sl1] = __uint_as_float(to_tf32(accS[nt][3]));
        }
        __syncwarp();

#pragma unroll
        for (int pc = 0; pc < 2; pc++) {
            const float* Pp = Ps + pc * PSZ;
            const float* Vp = Vt + pc * PSZ;
#pragma unroll
            for (int s = 0; s < 4; s++) {
                uint32_t af[4];
                const uint32_t* lo = (const uint32_t*)&Pp[rl0 * 40 + s * 8 + tg * 2];
                const uint32_t* hi = (const uint32_t*)&Pp[(rl0 + 8) * 40 + s * 8 + tg * 2];
                af[0] = lo[0]; af[2] = lo[1];
                af[1] = hi[0]; af[3] = hi[1];
#pragma unroll
                for (int nt = 0; nt < 8; nt++) {
                    uint32_t bf[2];
                    const uint32_t* bp = (const uint32_t*)&Vp[(nt * 8 + gid) * 40 + s * 8 + tg * 2];
                    bf[0] = bp[0]; bf[1] = bp[1];
                    mma_tf32(accO[nt], af, bf);
                }
            }
        }
    }

    // ---- finalize: write y' PERMUTED tf32 (A operand of proj GEMM)
    const float inv0 = 1.0f / l0;
    const float inv1 = 1.0f / l1;
    const int gr0 = q0 + rl0;
    const int gr1 = q0 + rl1;
    // position of col j within its 8-group: j<4 -> 2j ; else 2(j-4)+1
    const int p0 = (tg < 2) ? 4 * tg : 4 * tg - 7;       // for j = 2*tg
    const int p1 = (tg < 2) ? 4 * tg + 2 : 4 * tg - 5;   // for j = 2*tg+1
#pragma unroll
    for (int nt = 0; nt < 8; nt++) {
        const int cb = h * HS + nt * 8;
        yp[(size_t)gr0 * C_DIM + cb + p0] = __uint_as_float(to_tf32(accO[nt][0] * inv0));
        yp[(size_t)gr0 * C_DIM + cb + p1] = __uint_as_float(to_tf32(accO[nt][1] * inv0));
        yp[(size_t)gr1 * C_DIM + cb + p0] = __uint_as_float(to_tf32(accO[nt][2] * inv1));
        yp[(size_t)gr1 * C_DIM + cb + p1] = __uint_as_float(to_tf32(accO[nt][3] * inv1));
    }
}

// ---------------------------------------------------------------------------
extern "C" void kernel_launch(void* const* d_in, const int* in_sizes, int n_in,
                              void* d_out, int out_size)
{
    const float* x      = (const float*)d_in[0];   // [1,1024,768]
    const float* W_attn = (const float*)d_in[1];   // [768, 2304]
    const float* b_attn = (const float*)d_in[2];   // [2304]
    const float* W_proj = (const float*)d_in[3];   // [768, 768]
    const float* b_proj = (const float*)d_in[4];   // [768]
    float* out = (float*)d_out;                    // [1,1024,768]

    float *qkv, *y, *xp, *wa, *wp;
    cudaGetSymbolAddress((void**)&qkv, g_qkv);
    cudaGetSymbolAddress((void**)&y,   g_y);
    cudaGetSymbolAddress((void**)&xp,  g_xp);
    cudaGetSymbolAddress((void**)&wa,  g_wattn);
    cudaGetSymbolAddress((void**)&wp,  g_wproj);

    const int smem_qkv  = 3 * (128 + 128) * 40 * 4;   // 122880
    const int smem_proj = 3 * (64 + 128) * 40 * 4;    // 92160
    cudaFuncSetAttribute(gemm_cp<128, 128>,
                         cudaFuncAttributeMaxDynamicSharedMemorySize, smem_qkv);
    cudaFuncSetAttribute(gemm_cp<64, 128>,
                         cudaFuncAttributeMaxDynamicSharedMemorySize, smem_proj);
    cudaFuncSetAttribute(attn_kernel,
                         cudaFuncAttributeMaxDynamicSharedMemorySize, SM_ATTN_TOTAL);

    // 0) pre-passes: convert/permute operands to tf32 fragment-pair layouts
    permute_rows<<<(T_SEQ * C_DIM + 255) / 256, 256>>>(x, xp, T_SEQ * C_DIM);
    {
        dim3 grid(C3 / 32, C_DIM / 32);
        transpose_permute<<<grid, dim3(32, 8)>>>(W_attn, wa, C_DIM, C3);
    }
    {
        dim3 grid(C_DIM / 32, C_DIM / 32);
        transpose_permute<<<grid, dim3(32, 8)>>>(W_proj, wp, C_DIM, C_DIM);
    }

    // 1) qkv = x @ W_attn + b_attn   [1024, 2304]
    {
        dim3 grid(C3 / 128, T_SEQ / 128);   // (18, 8) = 144
        gemm_cp<128, 128><<<grid, 256, smem_qkv>>>(T_SEQ, C3, C_DIM, xp, wa, b_attn, qkv);
    }
    // 2) causal flash attention (tensor cores) -> y' permuted tf32
    {
        attn_kernel<<<(T_SEQ / 64) * NH, 128, SM_ATTN_TOTAL>>>(qkv, y);
    }
    // 3) out = y @ W_proj + b_proj   [1024, 768]
    {
        dim3 grid(C_DIM / 128, T_SEQ / 64);  // (6, 16) = 96
        gemm_cp<64, 128><<<grid, 256, smem_proj>>>(T_SEQ, C_DIM, C_DIM, y, wp, b_proj, out);
    }
}

// round 7
// speedup vs baseline: 3.6710x; 1.0366x over previous
#include <cuda_runtime.h>
#include <cstdint>
#include <math.h>

#define T_SEQ 1024
#define C_DIM 768
#define NH    12
#define HS    64
#define C3    (3 * C_DIM)   // 2304

// Scratch (allocation-free rule: __device__ globals)
__device__ float g_Qp[NH * T_SEQ * 64];      // Q pair-layout tf32 [h][t][64]
__device__ float g_Kp[NH * T_SEQ * 64];      // K pair-layout tf32 [h][t][64]
__device__ float g_Vt[NH * 32 * 64 * 32];    // V transposed tf32 [h][kgrp][dim][32]
__device__ float g_y[T_SEQ * C_DIM];         // attention out, PERMUTED tf32
__device__ float g_xp[T_SEQ * C_DIM];        // x permuted tf32
__device__ float g_wattn[C3 * C_DIM];        // W_attn^T permuted tf32 [2304][768]
__device__ float g_wproj[C_DIM * C_DIM];     // W_proj^T permuted tf32 [768][768]

// ---------------------------------------------------------------------------
// helpers
// ---------------------------------------------------------------------------
__device__ __forceinline__ uint32_t to_tf32(float f) {
    uint32_t u; asm("cvt.rna.tf32.f32 %0, %1;" : "=r"(u) : "f"(f)); return u;
}
__device__ __forceinline__ void mma_tf32(float* c, const uint32_t* a, const uint32_t* b) {
    asm volatile(
        "mma.sync.aligned.m16n8k8.row.col.f32.tf32.tf32.f32 "
        "{%0,%1,%2,%3},{%4,%5,%6,%7},{%8,%9},{%0,%1,%2,%3};"
        : "+f"(c[0]), "+f"(c[1]), "+f"(c[2]), "+f"(c[3])
        : "r"(a[0]), "r"(a[1]), "r"(a[2]), "r"(a[3]), "r"(b[0]), "r"(b[1]));
}
__device__ __forceinline__ float ex2(float x) {
    float r; asm("ex2.approx.f32 %0, %1;" : "=f"(r) : "f"(x)); return r;
}
__device__ __forceinline__ uint32_t smem_u32(const void* p) {
    uint32_t a;
    asm("{ .reg .u64 t; cvta.to.shared.u64 t, %1; cvt.u32.u64 %0, t; }" : "=r"(a) : "l"(p));
    return a;
}
__device__ __forceinline__ void cp16(uint32_t s, const void* g) {
    asm volatile("cp.async.cg.shared.global [%0], [%1], 16;" :: "r"(s), "l"(g) : "memory");
}
#define CP_COMMIT() asm volatile("cp.async.commit_group;" ::: "memory")
#define CP_WAIT1()  asm volatile("cp.async.wait_group 1;" ::: "memory")
#define CP_WAIT0()  asm volatile("cp.async.wait_group 0;" ::: "memory")

__device__ __forceinline__ int sigma8(int u) { return (u >> 1) + ((u & 1) << 2); }
__device__ __forceinline__ int pair_slot(int k) {   // k in [0,32)
    const int s = k >> 3, t = k & 7;
    return s * 8 + (t < 4 ? 2 * t : 2 * (t - 4) + 1);
}

extern __shared__ char sm_dyn[];

// ---------------------------------------------------------------------------
// Pre-pass 1: row-wise permute + tf32 convert (x)
// ---------------------------------------------------------------------------
__global__ void permute_rows(const float* __restrict__ in, float* __restrict__ out, int total)
{
    const int i = blockIdx.x * 256 + threadIdx.x;
    if (i >= total) return;
    const int row = i / C_DIM;
    const int k = i - row * C_DIM;
    const int src = (k & ~7) | sigma8(k & 7);
    out[i] = __uint_as_float(to_tf32(in[row * C_DIM + src]));
}

// ---------------------------------------------------------------------------
// Pre-pass 2: transpose + permute + tf32 convert for weights
// in: [K][N] row-major.  out: [N][K], out[n][g] = tf32(in[(g&~7)|sigma(g&7)][n])
// ---------------------------------------------------------------------------
__global__ void transpose_permute(const float* __restrict__ in, float* __restrict__ out,
                                  int K, int N)
{
    __shared__ float tile[32][33];
    const int tx = threadIdx.x;
    const int ty = threadIdx.y;
    const int n0 = blockIdx.x * 32;
    const int k0 = blockIdx.y * 32;
#pragma unroll
    for (int j = 0; j < 4; j++)
        tile[ty + 8 * j][tx] = in[(size_t)(k0 + ty + 8 * j) * N + n0 + tx];
    __syncthreads();
    const int src = (tx & ~7) | sigma8(tx & 7);
#pragma unroll
    for (int j = 0; j < 4; j++)
        out[(size_t)(n0 + ty + 8 * j) * K + k0 + tx] =
            __uint_as_float(to_tf32(tile[src][ty + 8 * j]));
}

// ---------------------------------------------------------------------------
// qkv GEMM: [1024,2304] = xp @ wa^T + b, scatter epilogue into Qp/Kp/Vt.
// BM=64, BN=128, BK=32, 3 cp.async stages, 256 threads (2x4 warps).
// ---------------------------------------------------------------------------
__global__ __launch_bounds__(256)
void gemm_qkv(const float* __restrict__ Ap,
              const float* __restrict__ Bp,
              const float* __restrict__ bias,
              float* __restrict__ Qp, float* __restrict__ Kp, float* __restrict__ Vt)
{
    constexpr int BM = 64, BN = 128, BK = 32, RS = 40, STG = 3;
    constexpr int K = C_DIM, N = C3;
    constexpr int SSA = BM * RS, SSB = BN * RS;
    constexpr int WM = 32, WN = 32, MT = 2, NT = 4;

    float* S = (float*)sm_dyn;
    const uint32_t sbase = smem_u32(S);

    const int tid  = threadIdx.x;
    const int wid  = tid >> 5;
    const int lane = tid & 31;
    const int gid  = lane >> 2;
    const int tg   = lane & 3;
    const int wm   = wid >> 2;
    const int wn   = wid & 3;
    const int m0   = blockIdx.y * BM;
    const int n0   = blockIdx.x * BN;

    const int arow = tid >> 3;
    const int ach  = tid & 7;

    float acc[MT][NT][4];
#pragma unroll
    for (int i = 0; i < MT; i++)
#pragma unroll
        for (int j = 0; j < NT; j++)
#pragma unroll
            for (int v = 0; v < 4; v++) acc[i][j][v] = 0.0f;

    auto issue_stage = [&](int i) {
        const int st = i % STG;
        const int kc = i * BK;
        const uint32_t ab = sbase + st * (SSA + SSB) * 4;
#pragma unroll
        for (int u = 0; u < BM / 32; u++) {
            const int row = arow + u * 32;
            cp16(ab + (row * RS + ach * 4) * 4, Ap + (size_t)(m0 + row) * K + kc + ach * 4);
        }
        const uint32_t bb = ab + SSA * 4;
#pragma unroll
        for (int u = 0; u < BN / 32; u++) {
            const int row = arow + u * 32;
            cp16(bb + (row * RS + ach * 4) * 4, Bp + (size_t)(n0 + row) * K + kc + ach * 4);
        }
        CP_COMMIT();
    };

    issue_stage(0);
    issue_stage(1);

    constexpr int nk = K / BK;
    for (int i = 0; i < nk; i++) {
        if (i + 1 < nk) CP_WAIT1(); else CP_WAIT0();
        __syncthreads();

        const int st = i % STG;
        const float* Aq = S + st * (SSA + SSB);
        const float* Bq = Aq + SSA;

#pragma unroll
        for (int s = 0; s < 4; s++) {
            uint32_t af[MT][4], bf[NT][2];
#pragma unroll
            for (int mt = 0; mt < MT; mt++) {
                const int row = wm * WM + mt * 16 + gid;
                const uint32_t* lo = (const uint32_t*)&Aq[row * RS + s * 8 + tg * 2];
                const uint32_t* hi = (const uint32_t*)&Aq[(row + 8) * RS + s * 8 + tg * 2];
                af[mt][0] = lo[0]; af[mt][2] = lo[1];
                af[mt][1] = hi[0]; af[mt][3] = hi[1];
            }
#pragma unroll
            for (int nt = 0; nt < NT; nt++) {
                const int n = wn * WN + nt * 8 + gid;
                const uint32_t* bp = (const uint32_t*)&Bq[n * RS + s * 8 + tg * 2];
                bf[nt][0] = bp[0]; bf[nt][1] = bp[1];
            }
#pragma unroll
            for (int mt = 0; mt < MT; mt++)
#pragma unroll
                for (int nt = 0; nt < NT; nt++)
                    mma_tf32(acc[mt][nt], af[mt], bf[nt]);
        }

        if (i + 2 < nk) issue_stage(i + 2);
    }

    // ---- scatter epilogue: whole block lies in one of Q/K/V (BN=128 | 768)
    const int sec = n0 / C_DIM;                    // 0=Q, 1=K, 2=V
    float* dst = (sec == 0) ? Qp : (sec == 1) ? Kp : Vt;
    const int ccb = n0 - sec * C_DIM + wn * WN;    // col within section

#pragma unroll
    for (int mt = 0; mt < MT; mt++) {
        const int r0 = m0 + wm * WM + mt * 16 + gid;
        const int r1 = r0 + 8;
#pragma unroll
        for (int nt = 0; nt < NT; nt++) {
            const int c = n0 + wn * WN + nt * 8 + 2 * tg;
            const float b0 = bias[c], b1 = bias[c + 1];
            const int cc0 = ccb + nt * 8 + 2 * tg;
            const int cc1 = cc0 + 1;
            const int h0 = cc0 >> 6, k0 = cc0 & 63;
            const int h1 = cc1 >> 6, k1 = cc1 & 63;
            float v00 = acc[mt][nt][0] + b0;   // (r0, cc0)
            float v01 = acc[mt][nt][1] + b1;   // (r0, cc1)
            float v10 = acc[mt][nt][2] + b0;   // (r1, cc0)
            float v11 = acc[mt][nt][3] + b1;   // (r1, cc1)
            if (sec < 2) {
                const int s0 = (k0 & 32) + pair_slot(k0 & 31);
                const int s1 = (k1 & 32) + pair_slot(k1 & 31);
                dst[h0 * 65536 + r0 * 64 + s0] = __uint_as_float(to_tf32(v00));
                dst[h1 * 65536 + r0 * 64 + s1] = __uint_as_float(to_tf32(v01));
                dst[h0 * 65536 + r1 * 64 + s0] = __uint_as_float(to_tf32(v10));
                dst[h1 * 65536 + r1 * 64 + s1] = __uint_as_float(to_tf32(v11));
            } else {
                const int g0 = (r0 >> 5) << 11;            // keygroup*2048
                const int g1 = (r1 >> 5) << 11;
                const int t0 = pair_slot(r0 & 31);
                const int t1 = pair_slot(r1 & 31);
                dst[h0 * 65536 + g0 + (k0 << 5) + t0] = __uint_as_float(to_tf32(v00));
                dst[h1 * 65536 + g0 + (k1 << 5) + t0] = __uint_as_float(to_tf32(v01));
                dst[h0 * 65536 + g1 + (k0 << 5) + t1] = __uint_as_float(to_tf32(v10));
                dst[h1 * 65536 + g1 + (k1 << 5) + t1] = __uint_as_float(to_tf32(v11));
            }
        }
    }
}

// ---------------------------------------------------------------------------
// proj GEMM: out[1024,768] = yp @ wp^T + bias (fp32 out). BM=BN=64.
// ---------------------------------------------------------------------------
__global__ __launch_bounds__(256)
void gemm_proj(const float* __restrict__ Ap,
               const float* __restrict__ Bp,
               const float* __restrict__ bias,
               float* __restrict__ C)
{
    constexpr int BM = 64, BN = 64, BK = 32, RS = 40, STG = 3;
    constexpr int K = C_DIM, N = C_DIM;
    constexpr int SSA = BM * RS, SSB = BN * RS;
    constexpr int WM = 32, WN = 16, MT = 2, NT = 2;

    float* S = (float*)sm_dyn;
    const uint32_t sbase = smem_u32(S);

    const int tid  = threadIdx.x;
    const int wid  = tid >> 5;
    const int lane = tid & 31;
    const int gid  = lane >> 2;
    const int tg   = lane & 3;
    const int wm   = wid >> 2;
    const int wn   = wid & 3;
    const int m0   = blockIdx.y * BM;
    const int n0   = blockIdx.x * BN;

    const int arow = tid >> 3;
    const int ach  = tid & 7;

    float acc[MT][NT][4];
#pragma unroll
    for (int i = 0; i < MT; i++)
#pragma unroll
        for (int j = 0; j < NT; j++)
#pragma unroll
            for (int v = 0; v < 4; v++) acc[i][j][v] = 0.0f;

    auto issue_stage = [&](int i) {
        const int st = i % STG;
        const int kc = i * BK;
        const uint32_t ab = sbase + st * (SSA + SSB) * 4;
#pragma unroll
        for (int u = 0; u < BM / 32; u++) {
            const int row = arow + u * 32;
            cp16(ab + (row * RS + ach * 4) * 4, Ap + (size_t)(m0 + row) * K + kc + ach * 4);
        }
        const uint32_t bb = ab + SSA * 4;
#pragma unroll
        for (int u = 0; u < BN / 32; u++) {
            const int row = arow + u * 32;
            cp16(bb + (row * RS + ach * 4) * 4, Bp + (size_t)(n0 + row) * K + kc + ach * 4);
        }
        CP_COMMIT();
    };

    issue_stage(0);
    issue_stage(1);

    constexpr int nk = K / BK;
    for (int i = 0; i < nk; i++) {
        if (i + 1 < nk) CP_WAIT1(); else CP_WAIT0();
        __syncthreads();

        const int st = i % STG;
        const float* Aq = S + st * (SSA + SSB);
        const float* Bq = Aq + SSA;

#pragma unroll
        for (int s = 0; s < 4; s++) {
            uint32_t af[MT][4], bf[NT][2];
#pragma unroll
            for (int mt = 0; mt < MT; mt++) {
                const int row = wm * WM + mt * 16 + gid;
                const uint32_t* lo = (const uint32_t*)&Aq[row * RS + s * 8 + tg * 2];
                const uint32_t* hi = (const uint32_t*)&Aq[(row + 8) * RS + s * 8 + tg * 2];
                af[mt][0] = lo[0]; af[mt][2] = lo[1];
                af[mt][1] = hi[0]; af[mt][3] = hi[1];
            }
#pragma unroll
            for (int nt = 0; nt < NT; nt++) {
                const int n = wn * WN + nt * 8 + gid;
                const uint32_t* bp = (const uint32_t*)&Bq[n * RS + s * 8 + tg * 2];
                bf[nt][0] = bp[0]; bf[nt][1] = bp[1];
            }
#pragma unroll
            for (int mt = 0; mt < MT; mt++)
#pragma unroll
                for (int nt = 0; nt < NT; nt++)
                    mma_tf32(acc[mt][nt], af[mt], bf[nt]);
        }

        if (i + 2 < nk) issue_stage(i + 2);
    }

#pragma unroll
    for (int mt = 0; mt < MT; mt++) {
        const int row = m0 + wm * WM + mt * 16 + gid;
#pragma unroll
        for (int nt = 0; nt < NT; nt++) {
            const int col = n0 + wn * WN + nt * 8 + 2 * tg;
            const float b0 = bias[col], b1 = bias[col + 1];
            float2 r0, r1;
            r0.x = acc[mt][nt][0] + b0; r0.y = acc[mt][nt][1] + b1;
            r1.x = acc[mt][nt][2] + b0; r1.y = acc[mt][nt][3] + b1;
            *(float2*)(C + (size_t)row * N + col)       = r0;
            *(float2*)(C + (size_t)(row + 8) * N + col) = r1;
        }
    }
}

// ---------------------------------------------------------------------------
// Tensor-core flash attention v2: Q in registers, K/V double-buffered cp.async
// from pre-permuted tf32 buffers. Block=(64 q-rows, head), 128 threads.
// smem: Kb[2 stages][2 panels][64][40] | Vb[same] | Ps[2][64][40]
// ---------------------------------------------------------------------------
#define PAN 2560                           // floats per panel (64*40)
#define SM_K 0
#define SM_V (4 * PAN * 4)                 // 40960
#define SM_P (8 * PAN * 4)                 // 81920
#define SM_ATTN_TOTAL (10 * PAN * 4)       // 102400

__global__ __launch_bounds__(128, 2)
void attn_kernel(const float* __restrict__ Qp, const float* __restrict__ Kp,
                 const float* __restrict__ Vt, float* __restrict__ yp)
{
    float* S  = (float*)sm_dyn;
    float* Kb = S;                // 4 panels (2 stages x 2)
    float* Vb = S + 4 * PAN;
    float* Ps = S + 8 * PAN;
    const uint32_t kbase = smem_u32(Kb);
    const uint32_t vbase = smem_u32(Vb);

    const int tid  = threadIdx.x;
    const int w    = tid >> 5;
    const int lane = tid & 31;
    const int gid  = lane >> 2;
    const int tg   = lane & 3;
    const int b    = blockIdx.x;
    const int qt   = 15 - (b / NH);
    const int h    = b % NH;
    const int q0   = qt * 64;
    const int rl0  = w * 16 + gid;
    const int rl1  = rl0 + 8;

    // ---- Q fragments in registers
    uint32_t qf[2][4][4];
    {
        const float* Q0 = Qp + h * 65536 + (size_t)(q0 + rl0) * 64;
        const float* Q1 = Qp + h * 65536 + (size_t)(q0 + rl1) * 64;
#pragma unroll
        for (int pc = 0; pc < 2; pc++)
#pragma unroll
            for (int s = 0; s < 4; s++) {
                float2 lo = *(const float2*)(Q0 + pc * 32 + s * 8 + tg * 2);
                float2 hi = *(const float2*)(Q1 + pc * 32 + s * 8 + tg * 2);
                qf[pc][s][0] = __float_as_uint(lo.x);
                qf[pc][s][1] = __float_as_uint(hi.x);
                qf[pc][s][2] = __float_as_uint(lo.y);
                qf[pc][s][3] = __float_as_uint(hi.y);
            }
    }

    // cp.async tile loaders (8 chunks per thread each)
    const int lr = tid >> 1;                // 0..63 (row / dim)
    const int lq = tid & 1;                 // panel-half selector
    auto issueK = [&](int kt, int st) {
        const float* src = Kp + h * 65536 + (size_t)(kt * 64) * 64;
        const uint32_t dstb = kbase + st * 2 * PAN * 4;
#pragma unroll
        for (int c = 0; c < 4; c++) {
            const int pc = (lq * 4 + c) >> 2;        // 0 or 1
            const int c4 = ((lq * 4 + c) & 3) * 8;   // 0,8,16,24
            cp16(dstb + (pc * PAN + lr * 40 + c4) * 4, src + lr * 64 + pc * 32 + c4);
            cp16(dstb + (pc * PAN + lr * 40 + c4 + 4) * 4, src + lr * 64 + pc * 32 + c4 + 4);
        }
        CP_COMMIT();
    };
    auto issueV = [&](int kt, int st) {
        const uint32_t dstb = vbase + st * 2 * PAN * 4;
#pragma unroll
        for (int c = 0; c < 4; c++) {
            const int pc = (lq * 4 + c) >> 2;
            const int c4 = ((lq * 4 + c) & 3) * 8;
            const float* src = Vt + h * 65536 + (2 * kt + pc) * 2048 + lr * 32;
            cp16(dstb + (pc * PAN + lr * 40 + c4) * 4, src + c4);
            cp16(dstb + (pc * PAN + lr * 40 + c4 + 4) * 4, src + c4 + 4);
        }
        CP_COMMIT();
    };

    float accO[8][4];
#pragma unroll
    for (int nt = 0; nt < 8; nt++)
#pragma unroll
        for (int v = 0; v < 4; v++) accO[nt][v] = 0.0f;
    float m0r = -1e30f, m1r = -1e30f, l0 = 0.0f, l1 = 0.0f;
    const float SC = 0.125f * 1.4426950408889634f;

    issueK(0, 0);
    issueV(0, 0);

    for (int kt = 0; kt <= qt; kt++) {
        const int st = kt & 1;

        CP_WAIT1();               // K(kt) complete (V(kt) may be pending)
        __syncthreads();

        // ---- S = Q K^T
        float accS[8][4];
#pragma unroll
        for (int nt = 0; nt < 8; nt++)
#pragma unroll
            for (int v = 0; v < 4; v++) accS[nt][v] = 0.0f;

        const float* Kq = Kb + st * 2 * PAN;
#pragma unroll
        for (int pc = 0; pc < 2; pc++)
#pragma unroll
            for (int s = 0; s < 4; s++) {
#pragma unroll
                for (int nt = 0; nt < 8; nt++) {
                    uint32_t bf[2];
                    const uint32_t* bp =
                        (const uint32_t*)&Kq[pc * PAN + (nt * 8 + gid) * 40 + s * 8 + tg * 2];
                    bf[0] = bp[0]; bf[1] = bp[1];
                    mma_tf32(accS[nt], qf[pc][s], bf);
                }
            }

        if (kt < qt) issueK(kt + 1, st ^ 1);

        // ---- mask + scale
        const bool diag = (kt == qt);
#pragma unroll
        for (int nt = 0; nt < 8; nt++) {
            const int c0 = nt * 8 + 2 * tg;
#pragma unroll
            for (int v = 0; v < 4; v++) accS[nt][v] *= SC;
            if (diag) {
                if (c0     > rl0) accS[nt][0] = -1e30f;
                if (c0 + 1 > rl0) accS[nt][1] = -1e30f;
                if (c0     > rl1) accS[nt][2] = -1e30f;
                if (c0 + 1 > rl1) accS[nt][3] = -1e30f;
            }
        }

        // ---- online softmax
        float mx0 = -1e30f, mx1 = -1e30f;
#pragma unroll
        for (int nt = 0; nt < 8; nt++) {
            mx0 = fmaxf(mx0, fmaxf(accS[nt][0], accS[nt][1]));
            mx1 = fmaxf(mx1, fmaxf(accS[nt][2], accS[nt][3]));
        }
        mx0 = fmaxf(mx0, __shfl_xor_sync(0xffffffffu, mx0, 1));
        mx0 = fmaxf(mx0, __shfl_xor_sync(0xffffffffu, mx0, 2));
        mx1 = fmaxf(mx1, __shfl_xor_sync(0xffffffffu, mx1, 1));
        mx1 = fmaxf(mx1, __shfl_xor_sync(0xffffffffu, mx1, 2));
        const float mn0 = fmaxf(m0r, mx0);
        const float mn1 = fmaxf(m1r, mx1);
        const float cr0 = ex2(m0r - mn0);
        const float cr1 = ex2(m1r - mn1);
        m0r = mn0; m1r = mn1;

        float ps0 = 0.0f, ps1 = 0.0f;
#pragma unroll
        for (int nt = 0; nt < 8; nt++) {
            accS[nt][0] = ex2(accS[nt][0] - mn0);
            accS[nt][1] = ex2(accS[nt][1] - mn0);
            accS[nt][2] = ex2(accS[nt][2] - mn1);
            accS[nt][3] = ex2(accS[nt][3] - mn1);
            ps0 += accS[nt][0] + accS[nt][1];
            ps1 += accS[nt][2] + accS[nt][3];
        }
        ps0 += __shfl_xor_sync(0xffffffffu, ps0, 1);
        ps0 += __shfl_xor_sync(0xffffffffu, ps0, 2);
        ps1 += __shfl_xor_sync(0xffffffffu, ps1, 1);
        ps1 += __shfl_xor_sync(0xffffffffu, ps1, 2);
        l0 = l0 * cr0 + ps0;
        l1 = l1 * cr1 + ps1;
#pragma unroll
        for (int nt = 0; nt < 8; nt++) {
            accO[nt][0] *= cr0; accO[nt][1] *= cr0;
            accO[nt][2] *= cr1; accO[nt][3] *= cr1;
        }

        // ---- wait V(kt), then Ps + PV
        if (kt < qt) CP_WAIT1(); else CP_WAIT0();
        __syncthreads();

        __syncwarp();
#pragma unroll
        for (int nt = 0; nt < 8; nt++) {
            const int c0   = nt * 8 + 2 * tg;
            const int pan0 = c0 >> 5;
            const int sl0  = pair_slot(c0 & 31);
            const int sl1  = pair_slot((c0 + 1) & 31);
            float* base0 = Ps + pan0 * PAN;
            base0[rl0 * 40 + sl0] = __uint_as_float(to_tf32(accS[nt][0]));
            base0[rl0 * 40 + sl1] = __uint_as_float(to_tf32(accS[nt][1]));
            base0[rl1 * 40 + sl0] = __uint_as_float(to_tf32(accS[nt][2]));
            base0[rl1 * 40 + sl1] = __uint_as_float(to_tf32(accS[nt][3]));
        }
        __syncwarp();

        const float* Vq = Vb + st * 2 * PAN;
#pragma unroll
        for (int pc = 0; pc < 2; pc++) {
            const float* Pp = Ps + pc * PAN;
#pragma unroll
            for (int s = 0; s < 4; s++) {
                uint32_t af[4];
                const uint32_t* lo = (const uint32_t*)&Pp[rl0 * 40 + s * 8 + tg * 2];
                const uint32_t* hi = (const uint32_t*)&Pp[rl1 * 40 + s * 8 + tg * 2];
                af[0] = lo[0]; af[2] = lo[1];
                af[1] = hi[0]; af[3] = hi[1];
#pragma unroll
                for (int nt = 0; nt < 8; nt++) {
                    uint32_t bf[2];
                    const uint32_t* bp =
                        (const uint32_t*)&Vq[pc * PAN + (nt * 8 + gid) * 40 + s * 8 + tg * 2];
                    bf[0] = bp[0]; bf[1] = bp[1];
                    mma_tf32(accO[nt], af, bf);
                }
            }
        }

        if (kt < qt) issueV(kt + 1, st ^ 1);
    }

    // ---- finalize: write y' PERMUTED tf32
    const float inv0 = 1.0f / l0;
    const float inv1 = 1.0f / l1;
    const int gr0 = q0 + rl0;
    const int gr1 = q0 + rl1;
    const int p0 = (tg < 2) ? 4 * tg : 4 * tg - 7;
    const int p1 = (tg < 2) ? 4 * tg + 2 : 4 * tg - 5;
#pragma unroll
    for (int nt = 0; nt < 8; nt++) {
        const int cb = h * HS + nt * 8;
        yp[(size_t)gr0 * C_DIM + cb + p0] = __uint_as_float(to_tf32(accO[nt][0] * inv0));
        yp[(size_t)gr0 * C_DIM + cb + p1] = __uint_as_float(to_tf32(accO[nt][1] * inv0));
        yp[(size_t)gr1 * C_DIM + cb + p0] = __uint_as_float(to_tf32(accO[nt][2] * inv1));
        yp[(size_t)gr1 * C_DIM + cb + p1] = __uint_as_float(to_tf32(accO[nt][3] * inv1));
    }
}

// ---------------------------------------------------------------------------
extern "C" void kernel_launch(void* const* d_in, const int* in_sizes, int n_in,
                              void* d_out, int out_size)
{
    const float* x      = (const float*)d_in[0];
    const float* W_attn = (const float*)d_in[1];
    const float* b_attn = (const float*)d_in[2];
    const float* W_proj = (const float*)d_in[3];
    const float* b_proj = (const float*)d_in[4];
    float* out = (float*)d_out;

    float *Qp, *Kp, *Vt, *y, *xp, *wa, *wp;
    cudaGetSymbolAddress((void**)&Qp, g_Qp);
    cudaGetSymbolAddress((void**)&Kp, g_Kp);
    cudaGetSymbolAddress((void**)&Vt, g_Vt);
    cudaGetSymbolAddress((void**)&y,  g_y);
    cudaGetSymbolAddress((void**)&xp, g_xp);
    cudaGetSymbolAddress((void**)&wa, g_wattn);
    cudaGetSymbolAddress((void**)&wp, g_wproj);

    const int smem_qkv  = 3 * (64 + 128) * 40 * 4;   // 92160
    const int smem_proj = 3 * (64 + 64) * 40 * 4;    // 61440
    cudaFuncSetAttribute(gemm_qkv, cudaFuncAttributeMaxDynamicSharedMemorySize, smem_qkv);
    cudaFuncSetAttribute(gemm_proj, cudaFuncAttributeMaxDynamicSharedMemorySize, smem_proj);
    cudaFuncSetAttribute(attn_kernel, cudaFuncAttributeMaxDynamicSharedMemorySize,
                         SM_ATTN_TOTAL);

    // 0) pre-passes
    permute_rows<<<(T_SEQ * C_DIM + 255) / 256, 256>>>(x, xp, T_SEQ * C_DIM);
    {
        dim3 grid(C3 / 32, C_DIM / 32);
        transpose_permute<<<grid, dim3(32, 8)>>>(W_attn, wa, C_DIM, C3);
    }
    {
        dim3 grid(C_DIM / 32, C_DIM / 32);
        transpose_permute<<<grid, dim3(32, 8)>>>(W_proj, wp, C_DIM, C_DIM);
    }

    // 1) qkv GEMM with scatter epilogue -> Qp/Kp/Vt
    {
        dim3 grid(C3 / 128, T_SEQ / 64);   // (18, 16) = 288
        gemm_qkv<<<grid, 256, smem_qkv>>>(xp, wa, b_attn, Qp, Kp, Vt);
    }
    // 2) attention (pipelined) -> y' permuted tf32
    {
        attn_kernel<<<(T_SEQ / 64) * NH, 128, SM_ATTN_TOTAL>>>(Qp, Kp, Vt, y);
    }
    // 3) proj GEMM -> out
    {
        dim3 grid(C_DIM / 64, T_SEQ / 64);  // (12, 16) = 192
        gemm_proj<<<grid, 256, smem_proj>>>(y, wp, b_proj, out);
    }
}

// round 8
// speedup vs baseline: 6.8260x; 1.8595x over previous
#include <cuda_runtime.h>
#include <cuda_fp16.h>
#include <cstdint>
#include <math.h>

#define T_SEQ 1024
#define C_DIM 768
#define NH    12
#define HS    64
#define C3    (3 * C_DIM)   // 2304

// Scratch (allocation-free rule: __device__ globals) — all fp16 operand buffers
__device__ __half g_Qp[NH * T_SEQ * 64];     // Q [h][t][64 dim-slots]
__device__ __half g_Kp[NH * T_SEQ * 64];     // K [h][t][64 dim-slots]
__device__ __half g_Vt[NH * 64 * T_SEQ];     // V [h][dim][1024 key-slots]
__device__ __half g_y[T_SEQ * C_DIM];        // attention out, permuted fp16
__device__ __half g_xp[T_SEQ * C_DIM];       // x permuted fp16
__device__ __half g_wattn[C3 * C_DIM];       // W_attn^T permuted fp16 [2304][768]
__device__ __half g_wproj[C_DIM * C_DIM];    // W_proj^T permuted fp16 [768][768]

// ---------------------------------------------------------------------------
// helpers
// ---------------------------------------------------------------------------
__device__ __forceinline__ void mma_f16(float* c, const uint32_t* a, const uint32_t* b) {
    asm volatile(
        "mma.sync.aligned.m16n8k16.row.col.f32.f16.f16.f32 "
        "{%0,%1,%2,%3},{%4,%5,%6,%7},{%8,%9},{%0,%1,%2,%3};"
        : "+f"(c[0]), "+f"(c[1]), "+f"(c[2]), "+f"(c[3])
        : "r"(a[0]), "r"(a[1]), "r"(a[2]), "r"(a[3]), "r"(b[0]), "r"(b[1]));
}
__device__ __forceinline__ float ex2(float x) {
    float r; asm("ex2.approx.f32 %0, %1;" : "=f"(r) : "f"(x)); return r;
}
__device__ __forceinline__ uint32_t smem_u32(const void* p) {
    uint32_t a;
    asm("{ .reg .u64 t; cvta.to.shared.u64 t, %1; cvt.u32.u64 %0, t; }" : "=r"(a) : "l"(p));
    return a;
}
__device__ __forceinline__ void cp16(uint32_t s, const void* g) {
    asm volatile("cp.async.cg.shared.global [%0], [%1], 16;" :: "r"(s), "l"(g) : "memory");
}
#define CP_COMMIT() asm volatile("cp.async.commit_group;" ::: "memory")
#define CP_WAIT1()  asm volatile("cp.async.wait_group 1;" ::: "memory")
#define CP_WAIT0()  asm volatile("cp.async.wait_group 0;" ::: "memory")

// 16-element k-group interleave: slot p holds source half src16(p);
// forward: half u lives at slot fwd16(u).
__device__ __forceinline__ int src16(int p) {            // p in [0,16)
    const int j = p >> 2, q = p & 3;
    return 2 * j + (q & 1) + 8 * (q >> 1);
}
__device__ __forceinline__ int fwd16(int u) {            // u in [0,16)
    const int j = u >> 1, e = u & 1;
    return (j < 4) ? 4 * j + e : 4 * j - 14 + e;
}

extern __shared__ char sm_dyn[];

// ---------------------------------------------------------------------------
// Pre-pass 1: row-wise permute + fp16 convert (x)
// ---------------------------------------------------------------------------
__global__ void permute_rows_h(const float* __restrict__ in, __half* __restrict__ out,
                               int total)
{
    const int i = blockIdx.x * 256 + threadIdx.x;
    if (i >= total) return;
    const int row = i / C_DIM;
    const int k = i - row * C_DIM;
    const int src = (k & ~15) | src16(k & 15);
    out[i] = __float2half_rn(in[row * C_DIM + src]);
}

// ---------------------------------------------------------------------------
// Pre-pass 2: transpose + permute + fp16 convert for weights
// in: [K][N] fp32 row-major. out: [N][K] fp16, out[n][p] = in[(p&~15)|src16(p&15)][n]
// ---------------------------------------------------------------------------
__global__ void transpose_permute_h(const float* __restrict__ in, __half* __restrict__ out,
                                    int K, int N)
{
    __shared__ float tile[32][33];
    const int tx = threadIdx.x;
    const int ty = threadIdx.y;
    const int n0 = blockIdx.x * 32;
    const int k0 = blockIdx.y * 32;
#pragma unroll
    for (int j = 0; j < 4; j++)
        tile[ty + 8 * j][tx] = in[(size_t)(k0 + ty + 8 * j) * N + n0 + tx];
    __syncthreads();
    const int src = (tx & ~15) | src16(tx & 15);
#pragma unroll
    for (int j = 0; j < 4; j++)
        out[(size_t)(n0 + ty + 8 * j) * K + k0 + tx] =
            __float2half_rn(tile[src][ty + 8 * j]);
}

// ---------------------------------------------------------------------------
// qkv GEMM (fp16 in, fp32 accum): [1024,2304] = xp @ wa^T + b,
// scatter epilogue into Qp/Kp/Vt. BM=128, BN=128, BK=64 halves, 3 stages.
// 256 threads = 8 warps (2x4). RS = 80 halves (160B rows).
// ---------------------------------------------------------------------------
__global__ __launch_bounds__(256)
void gemm_qkv(const __half* __restrict__ Ap,
              const __half* __restrict__ Bp,
              const float* __restrict__ bias,
              __half* __restrict__ Qp, __half* __restrict__ Kp, __half* __restrict__ Vt)
{
    constexpr int BM = 128, BN = 128, BK = 64, RS = 80, STG = 3;
    constexpr int K = C_DIM, N = C3;
    constexpr int SSH = (BM + BN) * RS;          // halves per stage
    constexpr int MT = 4, NT = 4;                // WM=64, WN=32

    __half* Sh = (__half*)sm_dyn;
    const uint32_t sbase = smem_u32(Sh);

    const int tid  = threadIdx.x;
    const int wid  = tid >> 5;
    const int lane = tid & 31;
    const int gid  = lane >> 2;
    const int tg   = lane & 3;
    const int wm   = wid >> 2;
    const int wn   = wid & 3;
    const int m0   = blockIdx.y * BM;
    const int n0   = blockIdx.x * BN;

    float acc[MT][NT][4];
#pragma unroll
    for (int i = 0; i < MT; i++)
#pragma unroll
        for (int j = 0; j < NT; j++)
#pragma unroll
            for (int v = 0; v < 4; v++) acc[i][j][v] = 0.0f;

    auto issue_stage = [&](int i) {
        const int st = i % STG;
        const int kc = i * BK;
        const uint32_t ab = sbase + st * SSH * 2;
#pragma unroll
        for (int u = 0; u < (BM * 8) / 256; u++) {       // 4
            const int c = tid + 256 * u;
            const int row = c >> 3, ch = c & 7;
            cp16(ab + row * (RS * 2) + ch * 16,
                 Ap + (size_t)(m0 + row) * K + kc + ch * 8);
        }
        const uint32_t bb = ab + BM * RS * 2;
#pragma unroll
        for (int u = 0; u < (BN * 8) / 256; u++) {       // 4
            const int c = tid + 256 * u;
            const int row = c >> 3, ch = c & 7;
            cp16(bb + row * (RS * 2) + ch * 16,
                 Bp + (size_t)(n0 + row) * K + kc + ch * 8);
        }
        CP_COMMIT();
    };

    issue_stage(0);
    issue_stage(1);

    constexpr int nk = K / BK;   // 12
    for (int i = 0; i < nk; i++) {
        if (i + 1 < nk) CP_WAIT1(); else CP_WAIT0();
        __syncthreads();

        const int st = i % STG;
        const __half* Aq = Sh + st * SSH;
        const __half* Bq = Aq + BM * RS;

#pragma unroll
        for (int g = 0; g < 4; g++) {                    // k16 groups
            uint32_t af[MT][4], bf[NT][2];
#pragma unroll
            for (int mt = 0; mt < MT; mt++) {
                const int row = wm * 64 + mt * 16 + gid;
                uint2 lo = *(const uint2*)&Aq[row * RS + g * 16 + tg * 4];
                uint2 hi = *(const uint2*)&Aq[(row + 8) * RS + g * 16 + tg * 4];
                af[mt][0] = lo.x; af[mt][1] = hi.x;
                af[mt][2] = lo.y; af[mt][3] = hi.y;
            }
#pragma unroll
            for (int nt = 0; nt < NT; nt++) {
                const int n = wn * 32 + nt * 8 + gid;
                uint2 bv = *(const uint2*)&Bq[n * RS + g * 16 + tg * 4];
                bf[nt][0] = bv.x; bf[nt][1] = bv.y;
            }
#pragma unroll
            for (int mt = 0; mt < MT; mt++)
#pragma unroll
                for (int nt = 0; nt < NT; nt++)
                    mma_f16(acc[mt][nt], af[mt], bf[nt]);
        }

        if (i + 2 < nk) issue_stage(i + 2);
    }

    // ---- scatter epilogue: this block lies fully in one of Q/K/V
    const int sec = n0 / C_DIM;                   // 0=Q, 1=K, 2=V
    const int ccb = n0 - sec * C_DIM + wn * 32;

#pragma unroll
    for (int mt = 0; mt < MT; mt++) {
        const int r0 = m0 + wm * 64 + mt * 16 + gid;
        const int r1 = r0 + 8;
#pragma unroll
        for (int nt = 0; nt < NT; nt++) {
            const int c = n0 + wn * 32 + nt * 8 + 2 * tg;
            const float b0 = bias[c], b1 = bias[c + 1];
            const int cc0 = ccb + nt * 8 + 2 * tg;
            const int h0 = cc0 >> 6, d0 = cc0 & 63;
            const float v00 = acc[mt][nt][0] + b0;
            const float v01 = acc[mt][nt][1] + b1;
            const float v10 = acc[mt][nt][2] + b0;
            const float v11 = acc[mt][nt][3] + b1;
            if (sec < 2) {
                __half* dst = (sec == 0) ? Qp : Kp;
                const int sl = (d0 & ~15) | fwd16(d0 & 15);   // d0 even -> sl even, sl+1 for d0+1
                *(__half2*)&dst[h0 * 65536 + r0 * 64 + sl] = __floats2half2_rn(v00, v01);
                *(__half2*)&dst[h0 * 65536 + r1 * 64 + sl] = __floats2half2_rn(v10, v11);
            } else {
                const int d1 = d0 + 1;
                const int t0 = (r0 & ~15) | fwd16(r0 & 15);
                const int t1 = (r1 & ~15) | fwd16(r1 & 15);
                Vt[h0 * 65536 + d0 * 1024 + t0] = __float2half_rn(v00);
                Vt[h0 * 65536 + d1 * 1024 + t0] = __float2half_rn(v01);
                Vt[h0 * 65536 + d0 * 1024 + t1] = __float2half_rn(v10);
                Vt[h0 * 65536 + d1 * 1024 + t1] = __float2half_rn(v11);
            }
        }
    }
}

// ---------------------------------------------------------------------------
// proj GEMM (fp16 in, fp32 out): out[1024,768] = yp @ wp^T + bias.
// BM=BN=64, BK=64, 3 stages, 256 threads.
// ---------------------------------------------------------------------------
__global__ __launch_bounds__(256)
void gemm_proj(const __half* __restrict__ Ap,
               const __half* __restrict__ Bp,
               const float* __restrict__ bias,
               float* __restrict__ C)
{
    constexpr int BM = 64, BN = 64, BK = 64, RS = 80, STG = 3;
    constexpr int K = C_DIM, N = C_DIM;
    constexpr int SSH = (BM + BN) * RS;
    constexpr int MT = 2, NT = 2;                // WM=32, WN=16

    __half* Sh = (__half*)sm_dyn;
    const uint32_t sbase = smem_u32(Sh);

    const int tid  = threadIdx.x;
    const int wid  = tid >> 5;
    const int lane = tid & 31;
    const int gid  = lane >> 2;
    const int tg   = lane & 3;
    const int wm   = wid >> 2;
    const int wn   = wid & 3;
    const int m0   = blockIdx.y * BM;
    const int n0   = blockIdx.x * BN;

    float acc[MT][NT][4];
#pragma unroll
    for (int i = 0; i < MT; i++)
#pragma unroll
        for (int j = 0; j < NT; j++)
#pragma unroll
            for (int v = 0; v < 4; v++) acc[i][j][v] = 0.0f;

    auto issue_stage = [&](int i) {
        const int st = i % STG;
        const int kc = i * BK;
        const uint32_t ab = sbase + st * SSH * 2;
#pragma unroll
        for (int u = 0; u < (BM * 8) / 256; u++) {       // 2
            const int c = tid + 256 * u;
            const int row = c >> 3, ch = c & 7;
            cp16(ab + row * (RS * 2) + ch * 16,
                 Ap + (size_t)(m0 + row) * K + kc + ch * 8);
        }
        const uint32_t bb = ab + BM * RS * 2;
#pragma unroll
        for (int u = 0; u < (BN * 8) / 256; u++) {       // 2
            const int c = tid + 256 * u;
            const int row = c >> 3, ch = c & 7;
            cp16(bb + row * (RS * 2) + ch * 16,
                 Bp + (size_t)(n0 + row) * K + kc + ch * 8);
        }
        CP_COMMIT();
    };

    issue_stage(0);
    issue_stage(1);

    constexpr int nk = K / BK;   // 12
    for (int i = 0; i < nk; i++) {
        if (i + 1 < nk) CP_WAIT1(); else CP_WAIT0();
        __syncthreads();

        const int st = i % STG;
        const __half* Aq = Sh + st * SSH;
        const __half* Bq = Aq + BM * RS;

#pragma unroll
        for (int g = 0; g < 4; g++) {
            uint32_t af[MT][4], bf[NT][2];
#pragma unroll
            for (int mt = 0; mt < MT; mt++) {
                const int row = wm * 32 + mt * 16 + gid;
                uint2 lo = *(const uint2*)&Aq[row * RS + g * 16 + tg * 4];
                uint2 hi = *(const uint2*)&Aq[(row + 8) * RS + g * 16 + tg * 4];
                af[mt][0] = lo.x; af[mt][1] = hi.x;
                af[mt][2] = lo.y; af[mt][3] = hi.y;
            }
#pragma unroll
            for (int nt = 0; nt < NT; nt++) {
                const int n = wn * 16 + nt * 8 + gid;
                uint2 bv = *(const uint2*)&Bq[n * RS + g * 16 + tg * 4];
                bf[nt][0] = bv.x; bf[nt][1] = bv.y;
            }
#pragma unroll
            for (int mt = 0; mt < MT; mt++)
#pragma unroll
                for (int nt = 0; nt < NT; nt++)
                    mma_f16(acc[mt][nt], af[mt], bf[nt]);
        }

        if (i + 2 < nk) issue_stage(i + 2);
    }

#pragma unroll
    for (int mt = 0; mt < MT; mt++) {
        const int row = m0 + wm * 32 + mt * 16 + gid;
#pragma unroll
        for (int nt = 0; nt < NT; nt++) {
            const int col = n0 + wn * 16 + nt * 8 + 2 * tg;
            const float b0 = bias[col], b1 = bias[col + 1];
            float2 r0, r1;
            r0.x = acc[mt][nt][0] + b0; r0.y = acc[mt][nt][1] + b1;
            r1.x = acc[mt][nt][2] + b0; r1.y = acc[mt][nt][3] + b1;
            *(float2*)(C + (size_t)row * N + col)       = r0;
            *(float2*)(C + (size_t)(row + 8) * N + col) = r1;
        }
    }
}

// ---------------------------------------------------------------------------
// fp16 tensor-core flash attention: Q in registers, K/V double-buffered
// cp.async, P as half2. Block=(64 q-rows, head), 128 threads, 4 CTAs/SM.
// smem (halves): Kb[2][64][80] | Vb[2][64][80] | Ps[64][80]  = 51200 B
// ---------------------------------------------------------------------------
#define KP 5120                    // halves per K/V buffer (64*80)
#define SM_ATTN_TOTAL (5 * KP * 2) // 51200 B

__global__ __launch_bounds__(128, 4)
void attn_kernel(const __half* __restrict__ Qp, const __half* __restrict__ Kp,
                 const __half* __restrict__ Vt, __half* __restrict__ yp)
{
    __half* Sh = (__half*)sm_dyn;
    __half* Kb = Sh;               // 2 buffers
    __half* Vb = Sh + 2 * KP;      // 2 buffers
    __half* Ps = Sh + 4 * KP;
    const uint32_t kbase = smem_u32(Kb);
    const uint32_t vbase = smem_u32(Vb);

    const int tid  = threadIdx.x;
    const int w    = tid >> 5;
    const int lane = tid & 31;
    const int gid  = lane >> 2;
    const int tg   = lane & 3;
    const int b    = blockIdx.x;
    const int qt   = 15 - (b / NH);
    const int h    = b % NH;
    const int q0   = qt * 64;
    const int rl0  = w * 16 + gid;
    const int rl1  = rl0 + 8;

    // ---- Q fragments in registers (4 k16-groups over HS=64)
    uint32_t qf[4][4];
    {
        const __half* Q0 = Qp + h * 65536 + (size_t)(q0 + rl0) * 64;
        const __half* Q1 = Qp + h * 65536 + (size_t)(q0 + rl1) * 64;
#pragma unroll
        for (int g = 0; g < 4; g++) {
            uint2 lo = *(const uint2*)(Q0 + g * 16 + tg * 4);
            uint2 hi = *(const uint2*)(Q1 + g * 16 + tg * 4);
            qf[g][0] = lo.x; qf[g][1] = hi.x;
            qf[g][2] = lo.y; qf[g][3] = hi.y;
        }
    }

    // cp.async loaders: 4 chunks of 16B per thread per tile
    auto issueK = [&](int kt, int st) {
        const __half* src = Kp + h * 65536 + (size_t)(kt * 64) * 64;
        const uint32_t dstb = kbase + st * KP * 2;
#pragma unroll
        for (int u = 0; u < 4; u++) {
            const int c = tid + 128 * u;
            const int row = c >> 3, ch = c & 7;
            cp16(dstb + row * 160 + ch * 16, src + row * 64 + ch * 8);
        }
        CP_COMMIT();
    };
    auto issueV = [&](int kt, int st) {
        const uint32_t dstb = vbase + st * KP * 2;
#pragma unroll
        for (int u = 0; u < 4; u++) {
            const int c = tid + 128 * u;
            const int row = c >> 3, ch = c & 7;   // row = dim
            cp16(dstb + row * 160 + ch * 16,
                 Vt + h * 65536 + row * 1024 + kt * 64 + ch * 8);
        }
        CP_COMMIT();
    };

    float accO[8][4];
#pragma unroll
    for (int nt = 0; nt < 8; nt++)
#pragma unroll
        for (int v = 0; v < 4; v++) accO[nt][v] = 0.0f;
    float m0r = -1e30f, m1r = -1e30f, l0 = 0.0f, l1 = 0.0f;
    const float SC = 0.125f * 1.4426950408889634f;

    issueK(0, 0);
    issueV(0, 0);

    for (int kt = 0; kt <= qt; kt++) {
        const int st = kt & 1;

        CP_WAIT1();               // K(kt) done (V(kt) may be pending)
        __syncthreads();

        // ---- S = Q K^T
        float accS[8][4];
#pragma unroll
        for (int nt = 0; nt < 8; nt++)
#pragma unroll
            for (int v = 0; v < 4; v++) accS[nt][v] = 0.0f;

        const __half* Kq = Kb + st * KP;
#pragma unroll
        for (int g = 0; g < 4; g++) {
#pragma unroll
            for (int nt = 0; nt < 8; nt++) {
                uint2 bv = *(const uint2*)&Kq[(nt * 8 + gid) * 80 + g * 16 + tg * 4];
                uint32_t bf[2] = {bv.x, bv.y};
                mma_f16(accS[nt], qf[g], bf);
            }
        }

        if (kt < qt) issueK(kt + 1, st ^ 1);

        // ---- mask + scale (log2 domain)
        const bool diag = (kt == qt);
#pragma unroll
        for (int nt = 0; nt < 8; nt++) {
            const int c0 = nt * 8 + 2 * tg;
#pragma unroll
            for (int v = 0; v < 4; v++) accS[nt][v] *= SC;
            if (diag) {
                if (c0     > rl0) accS[nt][0] = -1e30f;
                if (c0 + 1 > rl0) accS[nt][1] = -1e30f;
                if (c0     > rl1) accS[nt][2] = -1e30f;
                if (c0 + 1 > rl1) accS[nt][3] = -1e30f;
            }
        }

        // ---- online softmax
        float mx0 = -1e30f, mx1 = -1e30f;
#pragma unroll
        for (int nt = 0; nt < 8; nt++) {
            mx0 = fmaxf(mx0, fmaxf(accS[nt][0], accS[nt][1]));
            mx1 = fmaxf(mx1, fmaxf(accS[nt][2], accS[nt][3]));
        }
        mx0 = fmaxf(mx0, __shfl_xor_sync(0xffffffffu, mx0, 1));
        mx0 = fmaxf(mx0, __shfl_xor_sync(0xffffffffu, mx0, 2));
        mx1 = fmaxf(mx1, __shfl_xor_sync(0xffffffffu, mx1, 1));
        mx1 = fmaxf(mx1, __shfl_xor_sync(0xffffffffu, mx1, 2));
        const float mn0 = fmaxf(m0r, mx0);
        const float mn1 = fmaxf(m1r, mx1);
        const float cr0 = ex2(m0r - mn0);
        const float cr1 = ex2(m1r - mn1);
        m0r = mn0; m1r = mn1;

        float ps0 = 0.0f, ps1 = 0.0f;
#pragma unroll
        for (int nt = 0; nt < 8; nt++) {
            accS[nt][0] = ex2(accS[nt][0] - mn0);
            accS[nt][1] = ex2(accS[nt][1] - mn0);
            accS[nt][2] = ex2(accS[nt][2] - mn1);
            accS[nt][3] = ex2(accS[nt][3] - mn1);
            ps0 += accS[nt][0] + accS[nt][1];
            ps1 += accS[nt][2] + accS[nt][3];
        }
        ps0 += __shfl_xor_sync(0xffffffffu, ps0, 1);
        ps0 += __shfl_xor_sync(0xffffffffu, ps0, 2);
        ps1 += __shfl_xor_sync(0xffffffffu, ps1, 1);
        ps1 += __shfl_xor_sync(0xffffffffu, ps1, 2);
        l0 = l0 * cr0 + ps0;
        l1 = l1 * cr1 + ps1;
#pragma unroll
        for (int nt = 0; nt < 8; nt++) {
            accO[nt][0] *= cr0; accO[nt][1] *= cr0;
            accO[nt][2] *= cr1; accO[nt][3] *= cr1;
        }

        // ---- wait V(kt), then P store + PV
        if (kt < qt) CP_WAIT1(); else CP_WAIT0();
        __syncthreads();

        __syncwarp();
#pragma unroll
        for (int nt = 0; nt < 8; nt++) {
            const int c0 = nt * 8 + 2 * tg;
            const int sl = (c0 >> 4) * 16 + 4 * tg + 2 * (nt & 1);   // even
            *(__half2*)&Ps[rl0 * 80 + sl] = __floats2half2_rn(accS[nt][0], accS[nt][1]);
            *(__half2*)&Ps[rl1 * 80 + sl] = __floats2half2_rn(accS[nt][2], accS[nt][3]);
        }
        __syncwarp();

        const __half* Vq = Vb + st * KP;
#pragma unroll
        for (int g = 0; g < 4; g++) {       // k16 groups over 64 keys
            uint32_t af[4];
            uint2 lo = *(const uint2*)&Ps[rl0 * 80 + g * 16 + tg * 4];
            uint2 hi = *(const uint2*)&Ps[rl1 * 80 + g * 16 + tg * 4];
            af[0] = lo.x; af[1] = hi.x; af[2] = lo.y; af[3] = hi.y;
#pragma unroll
            for (int nt = 0; nt < 8; nt++) {
                uint2 bv = *(const uint2*)&Vq[(nt * 8 + gid) * 80 + g * 16 + tg * 4];
                uint32_t bf[2] = {bv.x, bv.y};
                mma_f16(accO[nt], af, bf);
            }
        }

        if (kt < qt) issueV(kt + 1, st ^ 1);
    }

    // ---- finalize: write y permuted fp16
    const float inv0 = 1.0f / l0;
    const float inv1 = 1.0f / l1;
    const int gr0 = q0 + rl0;
    const int gr1 = q0 + rl1;
#pragma unroll
    for (int nt = 0; nt < 8; nt++) {
        const int c0 = nt * 8 + 2 * tg;                          // dim within head
        const int sl = (c0 >> 4) * 16 + 4 * tg + 2 * (nt & 1);
        const int cb = h * 64 + sl;
        *(__half2*)&yp[(size_t)gr0 * C_DIM + cb] =
            __floats2half2_rn(accO[nt][0] * inv0, accO[nt][1] * inv0);
        *(__half2*)&yp[(size_t)gr1 * C_DIM + cb] =
            __floats2half2_rn(accO[nt][2] * inv1, accO[nt][3] * inv1);
    }
}

// ---------------------------------------------------------------------------
extern "C" void kernel_launch(void* const* d_in, const int* in_sizes, int n_in,
                              void* d_out, int out_size)
{
    const float* x      = (const float*)d_in[0];
    const float* W_attn = (const float*)d_in[1];
    const float* b_attn = (const float*)d_in[2];
    const float* W_proj = (const float*)d_in[3];
    const float* b_proj = (const float*)d_in[4];
    float* out = (float*)d_out;

    __half *Qp, *Kp, *Vt, *y, *xp, *wa, *wp;
    cudaGetSymbolAddress((void**)&Qp, g_Qp);
    cudaGetSymbolAddress((void**)&Kp, g_Kp);
    cudaGetSymbolAddress((void**)&Vt, g_Vt);
    cudaGetSymbolAddress((void**)&y,  g_y);
    cudaGetSymbolAddress((void**)&xp, g_xp);
    cudaGetSymbolAddress((void**)&wa, g_wattn);
    cudaGetSymbolAddress((void**)&wp, g_wproj);

    const int smem_qkv  = 3 * (128 + 128) * 80 * 2;   // 122880
    const int smem_proj = 3 * (64 + 64) * 80 * 2;     // 61440
    cudaFuncSetAttribute(gemm_qkv, cudaFuncAttributeMaxDynamicSharedMemorySize, smem_qkv);
    cudaFuncSetAttribute(gemm_proj, cudaFuncAttributeMaxDynamicSharedMemorySize, smem_proj);
    cudaFuncSetAttribute(attn_kernel, cudaFuncAttributeMaxDynamicSharedMemorySize,
                         SM_ATTN_TOTAL);

    // 0) pre-passes (fp32 -> fp16, permuted layouts)
    permute_rows_h<<<(T_SEQ * C_DIM + 255) / 256, 256>>>(x, xp, T_SEQ * C_DIM);
    {
        dim3 grid(C3 / 32, C_DIM / 32);
        transpose_permute_h<<<grid, dim3(32, 8)>>>(W_attn, wa, C_DIM, C3);
    }
    {
        dim3 grid(C_DIM / 32, C_DIM / 32);
        transpose_permute_h<<<grid, dim3(32, 8)>>>(W_proj, wp, C_DIM, C_DIM);
    }

    // 1) qkv GEMM with scatter epilogue -> Qp/Kp/Vt
    {
        dim3 grid(C3 / 128, T_SEQ / 128);   // (18, 8) = 144
        gemm_qkv<<<grid, 256, smem_qkv>>>(xp, wa, b_attn, Qp, Kp, Vt);
    }
    // 2) attention -> y (permuted fp16)
    {
        attn_kernel<<<(T_SEQ / 64) * NH, 128, SM_ATTN_TOTAL>>>(Qp, Kp, Vt, y);
    }
    // 3) proj GEMM -> out (fp32)
    {
        dim3 grid(C_DIM / 64, T_SEQ / 64);  // (12, 16) = 192
        gemm_proj<<<grid, 256, smem_proj>>>(y, wp, b_proj, out);
    }
}